// round 9
// baseline (speedup 1.0000x reference)
#include <cuda_runtime.h>
#include <cuda_bf16.h>
#include <stdint.h>

#define DINL __device__ __forceinline__

namespace {
constexpr int BATCH  = 2;
constexpr int SEQ    = 4096;
constexpr int DMODEL = 512;
constexpr int NH     = 8;
constexpr int DH     = 64;
constexpr int MROWS  = BATCH * SEQ;   // 8192
constexpr int NOUT   = 3 * DMODEL;    // 1536
constexpr int BHEADS = BATCH * NH;    // 16
constexpr float CSC  = 0.18033688011112042f;  // log2(e) / sqrt(64)

constexpr int ITILE  = 256;           // CTA i-rows (32 per warp)
constexpr int JTILE  = 64;
// dynamic smem layout (bytes)
constexpr int KSM_OFF  = 0;                       // 256 * 128 = 32768
constexpr int QSM_OFF0 = 32768;                   // 64 * 128 = 8192
constexpr int QSM_OFF1 = 40960;
constexpr int VSM_OFF0 = 49152;
constexpr int VSM_OFF1 = 57344;
constexpr int SMEM_BYTES = 65536;
}

// ---------------- scratch (device globals; no allocation allowed) ----------------
__device__ __nv_bfloat16 g_X[MROWS * DMODEL];
__device__ __nv_bfloat16 g_W[NOUT * DMODEL];     // rows [0,512)=Wv, [512,1536)=Wc
__device__ float         g_bias[NOUT];           // [0,512)=bv, [512,1536)=bc
__device__ __nv_bfloat16 g_K[BHEADS * SEQ * DH]; // pre-scaled by CSC
__device__ __nv_bfloat16 g_Q[BHEADS * SEQ * DH];
__device__ __nv_bfloat16 g_V[BHEADS * SEQ * DH];

// ---------------- helpers ----------------
DINL uint32_t swz(uint32_t r, uint32_t cByte) {
    return r * 128u + (cByte ^ ((r & 7u) << 4));
}

DINL void cpa16(uint32_t dst, const void* src) {
    asm volatile("cp.async.cg.shared.global [%0], [%1], 16;\n" :: "r"(dst), "l"(src));
}
DINL void cpa_commit() { asm volatile("cp.async.commit_group;\n"); }
template <int N> DINL void cpa_wait() { asm volatile("cp.async.wait_group %0;\n" :: "n"(N)); }

DINL void ldm4(uint32_t addr, uint32_t& r0, uint32_t& r1, uint32_t& r2, uint32_t& r3) {
    asm volatile("ldmatrix.sync.aligned.m8n8.x4.shared.b16 {%0,%1,%2,%3}, [%4];"
                 : "=r"(r0), "=r"(r1), "=r"(r2), "=r"(r3) : "r"(addr));
}
DINL void ldm4t(uint32_t addr, uint32_t& r0, uint32_t& r1, uint32_t& r2, uint32_t& r3) {
    asm volatile("ldmatrix.sync.aligned.m8n8.x4.trans.shared.b16 {%0,%1,%2,%3}, [%4];"
                 : "=r"(r0), "=r"(r1), "=r"(r2), "=r"(r3) : "r"(addr));
}

DINL void mma_bf16(float* c, uint32_t a0, uint32_t a1, uint32_t a2, uint32_t a3,
                   uint32_t b0, uint32_t b1) {
    asm volatile(
        "mma.sync.aligned.m16n8k16.row.col.f32.bf16.bf16.f32 "
        "{%0,%1,%2,%3}, {%4,%5,%6,%7}, {%8,%9}, {%0,%1,%2,%3};"
        : "+f"(c[0]), "+f"(c[1]), "+f"(c[2]), "+f"(c[3])
        : "r"(a0), "r"(a1), "r"(a2), "r"(a3), "r"(b0), "r"(b1));
}

DINL float rcpf_(float x) { float y; asm("rcp.approx.f32 %0, %1;" : "=f"(y) : "f"(x)); return y; }

DINL uint32_t packbf(float lo, float hi) {
    __nv_bfloat162 t = __floats2bfloat162_rn(lo, hi);
    return *reinterpret_cast<uint32_t*>(&t);
}

DINL uint32_t ex2bf2_(uint32_t x) {
    uint32_t y;
    asm("ex2.approx.ftz.bf16x2 %0, %1;" : "=r"(y) : "r"(x));
    return y;
}

// ---------------- convert kernels ----------------
__global__ void cvt_X_kernel(const float* __restrict__ x) {
    int i = blockIdx.x * 1024 + threadIdx.x;
    g_X[i] = __float2bfloat16(x[i]);
}

__global__ void cvt_W_kernel(const float* __restrict__ Wc, const float* __restrict__ bc,
                             const float* __restrict__ Wv, const float* __restrict__ bv) {
    int i = blockIdx.x * 1024 + threadIdx.x;
    int row = i >> 9;
    int col = i & 511;
    float v = (row < DMODEL) ? Wv[row * DMODEL + col] : Wc[(row - DMODEL) * DMODEL + col];
    g_W[i] = __float2bfloat16(v);
    if (i < NOUT) g_bias[i] = (i < DMODEL) ? bv[i] : bc[i - DMODEL];
}

// ---------------- projection GEMM: C[8192,1536] = X @ W^T + bias, scatter to K/Q/V ----------------
__global__ __launch_bounds__(256) void proj_kernel() {
    __shared__ __nv_bfloat16 As[2][128 * 64];
    __shared__ __nv_bfloat16 Bs[2][64 * 64];

    const int tid = threadIdx.x;
    const int lane = tid & 31;
    const int wid = tid >> 5;
    const int m0 = blockIdx.x * 128;
    const int n0 = blockIdx.y * 64;
    const int wm = (wid & 3) * 32;
    const int wn = (wid >> 2) * 32;

    uint32_t asb[2], bsb[2];
    asb[0] = (uint32_t)__cvta_generic_to_shared(As[0]);
    asb[1] = (uint32_t)__cvta_generic_to_shared(As[1]);
    bsb[0] = (uint32_t)__cvta_generic_to_shared(Bs[0]);
    bsb[1] = (uint32_t)__cvta_generic_to_shared(Bs[1]);

    auto issue = [&](int kc, int buf) {
        const int k0 = kc * 64;
#pragma unroll
        for (int i = 0; i < 4; i++) {
            int id = tid + i * 256;
            int r = id >> 3, ch = id & 7;
            cpa16(asb[buf] + swz(r, ch * 16), g_X + (size_t)(m0 + r) * DMODEL + k0 + ch * 8);
        }
#pragma unroll
        for (int i = 0; i < 2; i++) {
            int id = tid + i * 256;
            int r = id >> 3, ch = id & 7;
            cpa16(bsb[buf] + swz(r, ch * 16), g_W + (size_t)(n0 + r) * DMODEL + k0 + ch * 8);
        }
    };

    float acc[2][4][4] = {};

    issue(0, 0);
    cpa_commit();

    for (int kc = 0; kc < 8; kc++) {
        const int buf = kc & 1;
        __syncthreads();
        if (kc + 1 < 8) {
            issue(kc + 1, buf ^ 1);
            cpa_commit();
            cpa_wait<1>();
        } else {
            cpa_wait<0>();
        }
        __syncthreads();

#pragma unroll
        for (int kk = 0; kk < 4; kk++) {
            uint32_t a[2][4];
#pragma unroll
            for (int mt = 0; mt < 2; mt++) {
                int r = wm + mt * 16 + (lane & 7) + ((lane >> 3) & 1) * 8;
                int ch = kk * 2 + (lane >> 4);
                ldm4(asb[buf] + swz(r, ch * 16), a[mt][0], a[mt][1], a[mt][2], a[mt][3]);
            }
            uint32_t b[4][2];
#pragma unroll
            for (int p = 0; p < 2; p++) {
                int r = wn + p * 16 + (lane & 7) + ((lane >> 4) & 1) * 8;
                int ch = kk * 2 + ((lane >> 3) & 1);
                uint32_t r0, r1, r2, r3;
                ldm4(bsb[buf] + swz(r, ch * 16), r0, r1, r2, r3);
                b[p * 2][0] = r0; b[p * 2][1] = r1;
                b[p * 2 + 1][0] = r2; b[p * 2 + 1][1] = r3;
            }
#pragma unroll
            for (int mt = 0; mt < 2; mt++)
#pragma unroll
                for (int nt = 0; nt < 4; nt++)
                    mma_bf16(acc[mt][nt], a[mt][0], a[mt][1], a[mt][2], a[mt][3],
                             b[nt][0], b[nt][1]);
        }
    }

#pragma unroll
    for (int mt = 0; mt < 2; mt++) {
#pragma unroll
        for (int nt = 0; nt < 4; nt++) {
            int n = n0 + wn + nt * 8 + (lane & 3) * 2;
            float b0 = g_bias[n], b1 = g_bias[n + 1];
            int region = n >> 9;            // 0:K  1:Q  2:V
            int col = n & 511;
            int h = col >> 6;
            int d = col & 63;
            __nv_bfloat16* dst = (region == 0) ? g_K : ((region == 1) ? g_Q : g_V);
            float sc = (region == 0) ? CSC : 1.0f;
#pragma unroll
            for (int half = 0; half < 2; half++) {
                int m = m0 + wm + mt * 16 + (lane >> 2) + half * 8;
                int bb = m >> 12;
                int s = m & 4095;
                float v0 = (acc[mt][nt][half * 2 + 0] + b0) * sc;
                float v1 = (acc[mt][nt][half * 2 + 1] + b1) * sc;
                size_t off = ((size_t)(bb * NH + h) * SEQ + s) * DH + d;
                *reinterpret_cast<__nv_bfloat162*>(dst + off) = __floats2bfloat162_rn(v0, v1);
            }
        }
    }
}

// ---------------- attention kernel ----------------
// grid (SEQ/256, BHEADS); 8 warps, each owns a 32-row i-strip pair.
// Each Q/V fragment feeds MMAs for BOTH 16-row strips -> half the ldmatrix
// traffic per unit work. No-max log2-domain softmax; l via tensor-core P@ones.
__global__ __launch_bounds__(256, 1) void attn_kernel(const float* __restrict__ mfeat,
                                                      float* __restrict__ out) {
    extern __shared__ char smem[];
    const uint32_t smb = (uint32_t)__cvta_generic_to_shared(smem);
    const uint32_t ksb = smb + KSM_OFF;
    const uint32_t qsb[2] = { smb + QSM_OFF0, smb + QSM_OFF1 };
    const uint32_t vsb[2] = { smb + VSM_OFF0, smb + VSM_OFF1 };

    const int tid = threadIdx.x;
    const int lane = tid & 31;
    const int wid = tid >> 5;
    const int i0 = blockIdx.x * ITILE;
    const int bh = blockIdx.y;

    const __nv_bfloat16* Kg = g_K + (size_t)bh * SEQ * DH;
    const __nv_bfloat16* Qg = g_Q + (size_t)bh * SEQ * DH;
    const __nv_bfloat16* Vg = g_V + (size_t)bh * SEQ * DH;

    // K tile load (256 rows, resident; fragments hoisted to registers)
#pragma unroll
    for (int i = 0; i < 8; i++) {
        int id = tid + i * 256;
        int r = id >> 3, ch = id & 7;
        cpa16(ksb + swz(r, ch * 16), Kg + (size_t)(i0 + r) * DH + ch * 8);
    }
    cpa_commit();

    auto issue_qv = [&](int jt, int buf) {
        int j0 = jt * JTILE;
#pragma unroll
        for (int i = 0; i < 2; i++) {
            int id = tid + i * 256;
            int r = id >> 3, ch = id & 7;
            cpa16(qsb[buf] + swz(r, ch * 16), Qg + (size_t)(j0 + r) * DH + ch * 8);
            cpa16(vsb[buf] + swz(r, ch * 16), Vg + (size_t)(j0 + r) * DH + ch * 8);
        }
    };

    issue_qv(0, 0);
    cpa_commit();

    // wait for K, hoist K fragments for both strips
    cpa_wait<1>();
    __syncthreads();
    uint32_t kf[2][4][4];
#pragma unroll
    for (int st = 0; st < 2; st++) {
#pragma unroll
        for (int kk = 0; kk < 4; kk++) {
            int r = wid * 32 + st * 16 + (lane & 7) + ((lane >> 3) & 1) * 8;
            int ch = kk * 2 + (lane >> 4);
            ldm4(ksb + swz(r, ch * 16), kf[st][kk][0], kf[st][kk][1], kf[st][kk][2], kf[st][kk][3]);
        }
    }

    const uint32_t ONES2 = 0x3F803F80u;   // bf16x2 {1.0, 1.0}
    float lacc[2][4] = {};                // per-strip row sums via tensor core
    float o[2][8][4] = {};

    const int NT = SEQ / JTILE;

    for (int jt = 0; jt < NT; jt++) {
        const int buf = jt & 1;
        if (jt + 1 < NT) {
            issue_qv(jt + 1, buf ^ 1);
            cpa_commit();
            cpa_wait<1>();
        } else {
            cpa_wait<0>();
        }
        __syncthreads();

        // process the 64-j tile as 4 blocks of 16 j: QK -> exp -> PV
#pragma unroll
        for (int p = 0; p < 4; p++) {
            // ---- S(32x16) = K strips @ Q_block^T ----
            float s[2][2][4] = {};
#pragma unroll
            for (int kk = 0; kk < 4; kk++) {
                int r = p * 16 + (lane & 7) + ((lane >> 4) & 1) * 8;
                int ch = kk * 2 + ((lane >> 3) & 1);
                uint32_t b0, b1, b2, b3;
                ldm4(qsb[buf] + swz(r, ch * 16), b0, b1, b2, b3);
#pragma unroll
                for (int st = 0; st < 2; st++) {
                    mma_bf16(s[st][0], kf[st][kk][0], kf[st][kk][1], kf[st][kk][2], kf[st][kk][3], b0, b1);
                    mma_bf16(s[st][1], kf[st][kk][0], kf[st][kk][1], kf[st][kk][2], kf[st][kk][3], b2, b3);
                }
            }

            // ---- P = 2^S (bf16x2 MUFU), l += P@ones ----
            uint32_t pa[2][4];
#pragma unroll
            for (int st = 0; st < 2; st++) {
                pa[st][0] = ex2bf2_(packbf(s[st][0][0], s[st][0][1]));
                pa[st][1] = ex2bf2_(packbf(s[st][0][2], s[st][0][3]));
                pa[st][2] = ex2bf2_(packbf(s[st][1][0], s[st][1][1]));
                pa[st][3] = ex2bf2_(packbf(s[st][1][2], s[st][1][3]));
                mma_bf16(lacc[st], pa[st][0], pa[st][1], pa[st][2], pa[st][3], ONES2, ONES2);
            }

            // ---- O += P(32x16) @ V_block(16x64) ----
#pragma unroll
            for (int cb = 0; cb < 8; cb += 2) {
                int r = p * 16 + (lane & 7) + ((lane >> 3) & 1) * 8;
                int ch = cb + (lane >> 4);
                uint32_t b0, b1, b2, b3;
                ldm4t(vsb[buf] + swz(r, ch * 16), b0, b1, b2, b3);
#pragma unroll
                for (int st = 0; st < 2; st++) {
                    mma_bf16(o[st][cb + 0], pa[st][0], pa[st][1], pa[st][2], pa[st][3], b0, b1);
                    mma_bf16(o[st][cb + 1], pa[st][0], pa[st][1], pa[st][2], pa[st][3], b2, b3);
                }
            }
        }
        __syncthreads();
    }

    // ---- epilogue: out = m_feats + O / l ----
    const int b = bh >> 3;
    const int h = bh & 7;
#pragma unroll
    for (int st = 0; st < 2; st++) {
        float rl0 = rcpf_(lacc[st][0]);
        float rl1 = rcpf_(lacc[st][2]);
        const int gi0 = i0 + wid * 32 + st * 16 + (lane >> 2);
#pragma unroll
        for (int nt = 0; nt < 8; nt++) {
            int dcol = h * 64 + nt * 8 + (lane & 3) * 2;
            size_t idx0 = ((size_t)(b * SEQ + gi0)) * DMODEL + dcol;
            size_t idx1 = idx0 + (size_t)8 * DMODEL;
            float2 f0 = *reinterpret_cast<const float2*>(mfeat + idx0);
            float2 f1 = *reinterpret_cast<const float2*>(mfeat + idx1);
            float2 w0 = make_float2(f0.x + o[st][nt][0] * rl0, f0.y + o[st][nt][1] * rl0);
            float2 w1 = make_float2(f1.x + o[st][nt][2] * rl1, f1.y + o[st][nt][3] * rl1);
            *reinterpret_cast<float2*>(out + idx0) = w0;
            *reinterpret_cast<float2*>(out + idx1) = w1;
        }
    }
}

// ---------------- launch ----------------
extern "C" void kernel_launch(void* const* d_in, const int* in_sizes, int n_in,
                              void* d_out, int out_size) {
    const float* mf = (const float*)d_in[0];
    const float* Wc = (const float*)d_in[1];
    const float* bc = (const float*)d_in[2];
    const float* Wv = (const float*)d_in[3];
    const float* bv = (const float*)d_in[4];
    float* out = (float*)d_out;

    cudaFuncSetAttribute(attn_kernel, cudaFuncAttributeMaxDynamicSharedMemorySize, SMEM_BYTES);

    cvt_X_kernel<<<MROWS * DMODEL / 1024, 1024>>>(mf);
    cvt_W_kernel<<<NOUT * DMODEL / 1024, 1024>>>(Wc, bc, Wv, bv);
    proj_kernel<<<dim3(MROWS / 128, NOUT / 64), 256>>>();
    attn_kernel<<<dim3(SEQ / ITILE, BHEADS), 256, SMEM_BYTES>>>(mf, out);
}

// round 10
// speedup vs baseline: 1.0113x; 1.0113x over previous
#include <cuda_runtime.h>
#include <cuda_bf16.h>
#include <stdint.h>

#define DINL __device__ __forceinline__

namespace {
constexpr int BATCH  = 2;
constexpr int SEQ    = 4096;
constexpr int DMODEL = 512;
constexpr int NH     = 8;
constexpr int DH     = 64;
constexpr int MROWS  = BATCH * SEQ;   // 8192
constexpr int NOUT   = 3 * DMODEL;    // 1536
constexpr int BHEADS = BATCH * NH;    // 16
constexpr float CSC  = 0.18033688011112042f;  // log2(e) / sqrt(64)

constexpr int ITILE  = 256;           // CTA i-rows (32 per warp)
constexpr int JTILE  = 128;           // j-rows per pipeline stage
// dynamic smem layout (bytes)
constexpr int KSM_OFF  = 0;                       // 256 * 128 = 32768
constexpr int QSM_OFF0 = 32768;                   // 128 * 128 = 16384
constexpr int QSM_OFF1 = 49152;
constexpr int VSM_OFF0 = 65536;
constexpr int VSM_OFF1 = 81920;
constexpr int SMEM_BYTES = 98304;
}

// ---------------- scratch (device globals; no allocation allowed) ----------------
__device__ __nv_bfloat16 g_X[MROWS * DMODEL];
__device__ __nv_bfloat16 g_W[NOUT * DMODEL];     // rows [0,512)=Wv, [512,1536)=Wc
__device__ float         g_bias[NOUT];           // [0,512)=bv, [512,1536)=bc
__device__ __nv_bfloat16 g_K[BHEADS * SEQ * DH]; // pre-scaled by CSC
__device__ __nv_bfloat16 g_Q[BHEADS * SEQ * DH];
__device__ __nv_bfloat16 g_V[BHEADS * SEQ * DH];

// ---------------- helpers ----------------
DINL uint32_t swz(uint32_t r, uint32_t cByte) {
    return r * 128u + (cByte ^ ((r & 7u) << 4));
}

DINL void cpa16(uint32_t dst, const void* src) {
    asm volatile("cp.async.cg.shared.global [%0], [%1], 16;\n" :: "r"(dst), "l"(src));
}
DINL void cpa_commit() { asm volatile("cp.async.commit_group;\n"); }
template <int N> DINL void cpa_wait() { asm volatile("cp.async.wait_group %0;\n" :: "n"(N)); }

DINL void ldm4(uint32_t addr, uint32_t& r0, uint32_t& r1, uint32_t& r2, uint32_t& r3) {
    asm volatile("ldmatrix.sync.aligned.m8n8.x4.shared.b16 {%0,%1,%2,%3}, [%4];"
                 : "=r"(r0), "=r"(r1), "=r"(r2), "=r"(r3) : "r"(addr));
}
DINL void ldm4t(uint32_t addr, uint32_t& r0, uint32_t& r1, uint32_t& r2, uint32_t& r3) {
    asm volatile("ldmatrix.sync.aligned.m8n8.x4.trans.shared.b16 {%0,%1,%2,%3}, [%4];"
                 : "=r"(r0), "=r"(r1), "=r"(r2), "=r"(r3) : "r"(addr));
}

DINL void mma_bf16(float* c, uint32_t a0, uint32_t a1, uint32_t a2, uint32_t a3,
                   uint32_t b0, uint32_t b1) {
    asm volatile(
        "mma.sync.aligned.m16n8k16.row.col.f32.bf16.bf16.f32 "
        "{%0,%1,%2,%3}, {%4,%5,%6,%7}, {%8,%9}, {%0,%1,%2,%3};"
        : "+f"(c[0]), "+f"(c[1]), "+f"(c[2]), "+f"(c[3])
        : "r"(a0), "r"(a1), "r"(a2), "r"(a3), "r"(b0), "r"(b1));
}

DINL float rcpf_(float x) { float y; asm("rcp.approx.f32 %0, %1;" : "=f"(y) : "f"(x)); return y; }

DINL uint32_t packbf(float lo, float hi) {
    __nv_bfloat162 t = __floats2bfloat162_rn(lo, hi);
    return *reinterpret_cast<uint32_t*>(&t);
}

DINL uint32_t ex2bf2_(uint32_t x) {
    uint32_t y;
    asm("ex2.approx.ftz.bf16x2 %0, %1;" : "=r"(y) : "r"(x));
    return y;
}

// ---------------- convert kernels ----------------
__global__ void cvt_X_kernel(const float* __restrict__ x) {
    int i = blockIdx.x * 1024 + threadIdx.x;
    g_X[i] = __float2bfloat16(x[i]);
}

__global__ void cvt_W_kernel(const float* __restrict__ Wc, const float* __restrict__ bc,
                             const float* __restrict__ Wv, const float* __restrict__ bv) {
    int i = blockIdx.x * 1024 + threadIdx.x;
    int row = i >> 9;
    int col = i & 511;
    float v = (row < DMODEL) ? Wv[row * DMODEL + col] : Wc[(row - DMODEL) * DMODEL + col];
    g_W[i] = __float2bfloat16(v);
    if (i < NOUT) g_bias[i] = (i < DMODEL) ? bv[i] : bc[i - DMODEL];
}

// ---------------- projection GEMM: C[8192,1536] = X @ W^T + bias, scatter to K/Q/V ----------------
__global__ __launch_bounds__(256) void proj_kernel() {
    __shared__ __nv_bfloat16 As[2][128 * 64];
    __shared__ __nv_bfloat16 Bs[2][64 * 64];

    const int tid = threadIdx.x;
    const int lane = tid & 31;
    const int wid = tid >> 5;
    const int m0 = blockIdx.x * 128;
    const int n0 = blockIdx.y * 64;
    const int wm = (wid & 3) * 32;
    const int wn = (wid >> 2) * 32;

    uint32_t asb[2], bsb[2];
    asb[0] = (uint32_t)__cvta_generic_to_shared(As[0]);
    asb[1] = (uint32_t)__cvta_generic_to_shared(As[1]);
    bsb[0] = (uint32_t)__cvta_generic_to_shared(Bs[0]);
    bsb[1] = (uint32_t)__cvta_generic_to_shared(Bs[1]);

    auto issue = [&](int kc, int buf) {
        const int k0 = kc * 64;
#pragma unroll
        for (int i = 0; i < 4; i++) {
            int id = tid + i * 256;
            int r = id >> 3, ch = id & 7;
            cpa16(asb[buf] + swz(r, ch * 16), g_X + (size_t)(m0 + r) * DMODEL + k0 + ch * 8);
        }
#pragma unroll
        for (int i = 0; i < 2; i++) {
            int id = tid + i * 256;
            int r = id >> 3, ch = id & 7;
            cpa16(bsb[buf] + swz(r, ch * 16), g_W + (size_t)(n0 + r) * DMODEL + k0 + ch * 8);
        }
    };

    float acc[2][4][4] = {};

    issue(0, 0);
    cpa_commit();

    for (int kc = 0; kc < 8; kc++) {
        const int buf = kc & 1;
        __syncthreads();
        if (kc + 1 < 8) {
            issue(kc + 1, buf ^ 1);
            cpa_commit();
            cpa_wait<1>();
        } else {
            cpa_wait<0>();
        }
        __syncthreads();

#pragma unroll
        for (int kk = 0; kk < 4; kk++) {
            uint32_t a[2][4];
#pragma unroll
            for (int mt = 0; mt < 2; mt++) {
                int r = wm + mt * 16 + (lane & 7) + ((lane >> 3) & 1) * 8;
                int ch = kk * 2 + (lane >> 4);
                ldm4(asb[buf] + swz(r, ch * 16), a[mt][0], a[mt][1], a[mt][2], a[mt][3]);
            }
            uint32_t b[4][2];
#pragma unroll
            for (int p = 0; p < 2; p++) {
                int r = wn + p * 16 + (lane & 7) + ((lane >> 4) & 1) * 8;
                int ch = kk * 2 + ((lane >> 3) & 1);
                uint32_t r0, r1, r2, r3;
                ldm4(bsb[buf] + swz(r, ch * 16), r0, r1, r2, r3);
                b[p * 2][0] = r0; b[p * 2][1] = r1;
                b[p * 2 + 1][0] = r2; b[p * 2 + 1][1] = r3;
            }
#pragma unroll
            for (int mt = 0; mt < 2; mt++)
#pragma unroll
                for (int nt = 0; nt < 4; nt++)
                    mma_bf16(acc[mt][nt], a[mt][0], a[mt][1], a[mt][2], a[mt][3],
                             b[nt][0], b[nt][1]);
        }
    }

#pragma unroll
    for (int mt = 0; mt < 2; mt++) {
#pragma unroll
        for (int nt = 0; nt < 4; nt++) {
            int n = n0 + wn + nt * 8 + (lane & 3) * 2;
            float b0 = g_bias[n], b1 = g_bias[n + 1];
            int region = n >> 9;            // 0:K  1:Q  2:V
            int col = n & 511;
            int h = col >> 6;
            int d = col & 63;
            __nv_bfloat16* dst = (region == 0) ? g_K : ((region == 1) ? g_Q : g_V);
            float sc = (region == 0) ? CSC : 1.0f;
#pragma unroll
            for (int half = 0; half < 2; half++) {
                int m = m0 + wm + mt * 16 + (lane >> 2) + half * 8;
                int bb = m >> 12;
                int s = m & 4095;
                float v0 = (acc[mt][nt][half * 2 + 0] + b0) * sc;
                float v1 = (acc[mt][nt][half * 2 + 1] + b1) * sc;
                size_t off = ((size_t)(bb * NH + h) * SEQ + s) * DH + d;
                *reinterpret_cast<__nv_bfloat162*>(dst + off) = __floats2bfloat162_rn(v0, v1);
            }
        }
    }
}

// ---------------- attention kernel ----------------
// grid (SEQ/256, BHEADS); 8 warps, each owns a 32-row i-strip pair.
// Software-pipelined inner loop: exp(block p) is issued, then QK MMAs of
// block p+1 fill the MUFU latency, then PV(block p) consumes. No-max
// log2-domain softmax; l via tensor-core P@ones.
__global__ __launch_bounds__(256, 1) void attn_kernel(const float* __restrict__ mfeat,
                                                      float* __restrict__ out) {
    extern __shared__ char smem[];
    const uint32_t smb = (uint32_t)__cvta_generic_to_shared(smem);
    const uint32_t ksb = smb + KSM_OFF;
    const uint32_t qsb[2] = { smb + QSM_OFF0, smb + QSM_OFF1 };
    const uint32_t vsb[2] = { smb + VSM_OFF0, smb + VSM_OFF1 };

    const int tid = threadIdx.x;
    const int lane = tid & 31;
    const int wid = tid >> 5;
    const int i0 = blockIdx.x * ITILE;
    const int bh = blockIdx.y;

    const __nv_bfloat16* Kg = g_K + (size_t)bh * SEQ * DH;
    const __nv_bfloat16* Qg = g_Q + (size_t)bh * SEQ * DH;
    const __nv_bfloat16* Vg = g_V + (size_t)bh * SEQ * DH;

    // K tile load (256 rows, resident; fragments hoisted to registers)
#pragma unroll
    for (int i = 0; i < 8; i++) {
        int id = tid + i * 256;
        int r = id >> 3, ch = id & 7;
        cpa16(ksb + swz(r, ch * 16), Kg + (size_t)(i0 + r) * DH + ch * 8);
    }
    cpa_commit();

    auto issue_qv = [&](int jt, int buf) {
        int j0 = jt * JTILE;
#pragma unroll
        for (int i = 0; i < 4; i++) {
            int id = tid + i * 256;
            int r = id >> 3, ch = id & 7;
            cpa16(qsb[buf] + swz(r, ch * 16), Qg + (size_t)(j0 + r) * DH + ch * 8);
            cpa16(vsb[buf] + swz(r, ch * 16), Vg + (size_t)(j0 + r) * DH + ch * 8);
        }
    };

    issue_qv(0, 0);
    cpa_commit();

    // wait for K, hoist K fragments for both strips
    cpa_wait<1>();
    __syncthreads();
    uint32_t kf[2][4][4];
#pragma unroll
    for (int st = 0; st < 2; st++) {
#pragma unroll
        for (int kk = 0; kk < 4; kk++) {
            int r = wid * 32 + st * 16 + (lane & 7) + ((lane >> 3) & 1) * 8;
            int ch = kk * 2 + (lane >> 4);
            ldm4(ksb + swz(r, ch * 16), kf[st][kk][0], kf[st][kk][1], kf[st][kk][2], kf[st][kk][3]);
        }
    }

    const uint32_t ONES2 = 0x3F803F80u;   // bf16x2 {1.0, 1.0}
    float lacc[2][4] = {};                // per-strip row sums via tensor core
    float o[2][8][4] = {};

    const int NT = SEQ / JTILE;
    constexpr int NP = JTILE / 16;        // 16-j blocks per stage

    for (int jt = 0; jt < NT; jt++) {
        const int buf = jt & 1;
        if (jt + 1 < NT) {
            issue_qv(jt + 1, buf ^ 1);
            cpa_commit();
            cpa_wait<1>();
        } else {
            cpa_wait<0>();
        }
        __syncthreads();

        // QK of one 16-j block into s
        auto qk = [&](int p, float (&s)[2][2][4]) {
#pragma unroll
            for (int st = 0; st < 2; st++)
#pragma unroll
                for (int a = 0; a < 2; a++)
#pragma unroll
                    for (int e = 0; e < 4; e++) s[st][a][e] = 0.f;
#pragma unroll
            for (int kk = 0; kk < 4; kk++) {
                int r = p * 16 + (lane & 7) + ((lane >> 4) & 1) * 8;
                int ch = kk * 2 + ((lane >> 3) & 1);
                uint32_t b0, b1, b2, b3;
                ldm4(qsb[buf] + swz(r, ch * 16), b0, b1, b2, b3);
#pragma unroll
                for (int st = 0; st < 2; st++) {
                    mma_bf16(s[st][0], kf[st][kk][0], kf[st][kk][1], kf[st][kk][2], kf[st][kk][3], b0, b1);
                    mma_bf16(s[st][1], kf[st][kk][0], kf[st][kk][1], kf[st][kk][2], kf[st][kk][3], b2, b3);
                }
            }
        };

        float sA[2][2][4], sB[2][2][4];
        qk(0, sA);

#pragma unroll
        for (int p = 0; p < NP; p++) {
            float (&sc)[2][2][4] = (p & 1) ? sB : sA;
            float (&sn)[2][2][4] = (p & 1) ? sA : sB;

            // exp of current block (MUFU; latency hidden by next QK below)
            uint32_t pa[2][4];
#pragma unroll
            for (int st = 0; st < 2; st++) {
                pa[st][0] = ex2bf2_(packbf(sc[st][0][0], sc[st][0][1]));
                pa[st][1] = ex2bf2_(packbf(sc[st][0][2], sc[st][0][3]));
                pa[st][2] = ex2bf2_(packbf(sc[st][1][0], sc[st][1][1]));
                pa[st][3] = ex2bf2_(packbf(sc[st][1][2], sc[st][1][3]));
            }

            // QK of next block — independent MMAs fill the MUFU latency
            if (p + 1 < NP) qk(p + 1, sn);

            // O += P(32x16) @ V_block(16x64)
#pragma unroll
            for (int cb = 0; cb < 8; cb += 2) {
                int r = p * 16 + (lane & 7) + ((lane >> 3) & 1) * 8;
                int ch = cb + (lane >> 4);
                uint32_t b0, b1, b2, b3;
                ldm4t(vsb[buf] + swz(r, ch * 16), b0, b1, b2, b3);
#pragma unroll
                for (int st = 0; st < 2; st++) {
                    mma_bf16(o[st][cb + 0], pa[st][0], pa[st][1], pa[st][2], pa[st][3], b0, b1);
                    mma_bf16(o[st][cb + 1], pa[st][0], pa[st][1], pa[st][2], pa[st][3], b2, b3);
                }
            }

            // l += P @ ones
#pragma unroll
            for (int st = 0; st < 2; st++)
                mma_bf16(lacc[st], pa[st][0], pa[st][1], pa[st][2], pa[st][3], ONES2, ONES2);
        }
        __syncthreads();
    }

    // ---- epilogue: out = m_feats + O / l ----
    const int b = bh >> 3;
    const int h = bh & 7;
#pragma unroll
    for (int st = 0; st < 2; st++) {
        float rl0 = rcpf_(lacc[st][0]);
        float rl1 = rcpf_(lacc[st][2]);
        const int gi0 = i0 + wid * 32 + st * 16 + (lane >> 2);
#pragma unroll
        for (int nt = 0; nt < 8; nt++) {
            int dcol = h * 64 + nt * 8 + (lane & 3) * 2;
            size_t idx0 = ((size_t)(b * SEQ + gi0)) * DMODEL + dcol;
            size_t idx1 = idx0 + (size_t)8 * DMODEL;
            float2 f0 = *reinterpret_cast<const float2*>(mfeat + idx0);
            float2 f1 = *reinterpret_cast<const float2*>(mfeat + idx1);
            float2 w0 = make_float2(f0.x + o[st][nt][0] * rl0, f0.y + o[st][nt][1] * rl0);
            float2 w1 = make_float2(f1.x + o[st][nt][2] * rl1, f1.y + o[st][nt][3] * rl1);
            *reinterpret_cast<float2*>(out + idx0) = w0;
            *reinterpret_cast<float2*>(out + idx1) = w1;
        }
    }
}

// ---------------- launch ----------------
extern "C" void kernel_launch(void* const* d_in, const int* in_sizes, int n_in,
                              void* d_out, int out_size) {
    const float* mf = (const float*)d_in[0];
    const float* Wc = (const float*)d_in[1];
    const float* bc = (const float*)d_in[2];
    const float* Wv = (const float*)d_in[3];
    const float* bv = (const float*)d_in[4];
    float* out = (float*)d_out;

    cudaFuncSetAttribute(attn_kernel, cudaFuncAttributeMaxDynamicSharedMemorySize, SMEM_BYTES);

    cvt_X_kernel<<<MROWS * DMODEL / 1024, 1024>>>(mf);
    cvt_W_kernel<<<NOUT * DMODEL / 1024, 1024>>>(Wc, bc, Wv, bv);
    proj_kernel<<<dim3(MROWS / 128, NOUT / 64), 256>>>();
    attn_kernel<<<dim3(SEQ / ITILE, BHEADS), 256, SMEM_BYTES>>>(mf, out);
}

// round 12
// speedup vs baseline: 1.0357x; 1.0241x over previous
#include <cuda_runtime.h>
#include <cuda_bf16.h>
#include <stdint.h>

#define DINL __device__ __forceinline__

namespace {
constexpr int BATCH  = 2;
constexpr int SEQ    = 4096;
constexpr int DMODEL = 512;
constexpr int NH     = 8;
constexpr int DH     = 64;
constexpr int MROWS  = BATCH * SEQ;   // 8192
constexpr int NOUT   = 3 * DMODEL;    // 1536
constexpr int BHEADS = BATCH * NH;    // 16
constexpr float CSC  = 0.18033688011112042f;  // log2(e) / sqrt(64)

constexpr int ITILE  = 128;           // CTA i-rows (32 per warp, 4 warps)
constexpr int JTILE  = 64;            // j-rows per stage
// dynamic smem layout (bytes)
constexpr int KSM_OFF  = 0;                       // 128 * 128 = 16384
constexpr int QSM_OFF0 = 16384;                   // 64 * 128 = 8192
constexpr int QSM_OFF1 = 24576;
constexpr int VSM_OFF0 = 32768;
constexpr int VSM_OFF1 = 40960;
constexpr int SMEM_BYTES = 49152;                 // 48 KB -> 2 CTAs/SM
}

// ---------------- scratch (device globals; no allocation allowed) ----------------
__device__ __nv_bfloat16 g_X[MROWS * DMODEL];
__device__ __nv_bfloat16 g_W[NOUT * DMODEL];     // rows [0,512)=Wv, [512,1536)=Wc
__device__ float         g_bias[NOUT];           // [0,512)=bv, [512,1536)=bc
__device__ __nv_bfloat16 g_K[BHEADS * SEQ * DH]; // pre-scaled by CSC
__device__ __nv_bfloat16 g_Q[BHEADS * SEQ * DH];
__device__ __nv_bfloat16 g_V[BHEADS * SEQ * DH];

// ---------------- helpers ----------------
DINL uint32_t swz(uint32_t r, uint32_t cByte) {
    return r * 128u + (cByte ^ ((r & 7u) << 4));
}

DINL void cpa16(uint32_t dst, const void* src) {
    asm volatile("cp.async.cg.shared.global [%0], [%1], 16;\n" :: "r"(dst), "l"(src));
}
DINL void cpa_commit() { asm volatile("cp.async.commit_group;\n"); }
template <int N> DINL void cpa_wait() { asm volatile("cp.async.wait_group %0;\n" :: "n"(N)); }

DINL void ldm4(uint32_t addr, uint32_t& r0, uint32_t& r1, uint32_t& r2, uint32_t& r3) {
    asm volatile("ldmatrix.sync.aligned.m8n8.x4.shared.b16 {%0,%1,%2,%3}, [%4];"
                 : "=r"(r0), "=r"(r1), "=r"(r2), "=r"(r3) : "r"(addr));
}
DINL void ldm4t(uint32_t addr, uint32_t& r0, uint32_t& r1, uint32_t& r2, uint32_t& r3) {
    asm volatile("ldmatrix.sync.aligned.m8n8.x4.trans.shared.b16 {%0,%1,%2,%3}, [%4];"
                 : "=r"(r0), "=r"(r1), "=r"(r2), "=r"(r3) : "r"(addr));
}

DINL void mma_bf16(float* c, uint32_t a0, uint32_t a1, uint32_t a2, uint32_t a3,
                   uint32_t b0, uint32_t b1) {
    asm volatile(
        "mma.sync.aligned.m16n8k16.row.col.f32.bf16.bf16.f32 "
        "{%0,%1,%2,%3}, {%4,%5,%6,%7}, {%8,%9}, {%0,%1,%2,%3};"
        : "+f"(c[0]), "+f"(c[1]), "+f"(c[2]), "+f"(c[3])
        : "r"(a0), "r"(a1), "r"(a2), "r"(a3), "r"(b0), "r"(b1));
}

DINL float rcpf_(float x) { float y; asm("rcp.approx.f32 %0, %1;" : "=f"(y) : "f"(x)); return y; }

DINL uint32_t packbf(float lo, float hi) {
    __nv_bfloat162 t = __floats2bfloat162_rn(lo, hi);
    return *reinterpret_cast<uint32_t*>(&t);
}

DINL uint32_t ex2bf2_(uint32_t x) {
    uint32_t y;
    asm("ex2.approx.ftz.bf16x2 %0, %1;" : "=r"(y) : "r"(x));
    return y;
}

// ---------------- convert kernels ----------------
__global__ void cvt_X_kernel(const float* __restrict__ x) {
    int i = blockIdx.x * 1024 + threadIdx.x;
    g_X[i] = __float2bfloat16(x[i]);
}

__global__ void cvt_W_kernel(const float* __restrict__ Wc, const float* __restrict__ bc,
                             const float* __restrict__ Wv, const float* __restrict__ bv) {
    int i = blockIdx.x * 1024 + threadIdx.x;
    int row = i >> 9;
    int col = i & 511;
    float v = (row < DMODEL) ? Wv[row * DMODEL + col] : Wc[(row - DMODEL) * DMODEL + col];
    g_W[i] = __float2bfloat16(v);
    if (i < NOUT) g_bias[i] = (i < DMODEL) ? bv[i] : bc[i - DMODEL];
}

// ---------------- projection GEMM: C[8192,1536] = X @ W^T + bias, scatter to K/Q/V ----------------
__global__ __launch_bounds__(256) void proj_kernel() {
    __shared__ __nv_bfloat16 As[2][128 * 64];
    __shared__ __nv_bfloat16 Bs[2][64 * 64];

    const int tid = threadIdx.x;
    const int lane = tid & 31;
    const int wid = tid >> 5;
    const int m0 = blockIdx.x * 128;
    const int n0 = blockIdx.y * 64;
    const int wm = (wid & 3) * 32;
    const int wn = (wid >> 2) * 32;

    uint32_t asb[2], bsb[2];
    asb[0] = (uint32_t)__cvta_generic_to_shared(As[0]);
    asb[1] = (uint32_t)__cvta_generic_to_shared(As[1]);
    bsb[0] = (uint32_t)__cvta_generic_to_shared(Bs[0]);
    bsb[1] = (uint32_t)__cvta_generic_to_shared(Bs[1]);

    auto issue = [&](int kc, int buf) {
        const int k0 = kc * 64;
#pragma unroll
        for (int i = 0; i < 4; i++) {
            int id = tid + i * 256;
            int r = id >> 3, ch = id & 7;
            cpa16(asb[buf] + swz(r, ch * 16), g_X + (size_t)(m0 + r) * DMODEL + k0 + ch * 8);
        }
#pragma unroll
        for (int i = 0; i < 2; i++) {
            int id = tid + i * 256;
            int r = id >> 3, ch = id & 7;
            cpa16(bsb[buf] + swz(r, ch * 16), g_W + (size_t)(n0 + r) * DMODEL + k0 + ch * 8);
        }
    };

    float acc[2][4][4] = {};

    issue(0, 0);
    cpa_commit();

    for (int kc = 0; kc < 8; kc++) {
        const int buf = kc & 1;
        __syncthreads();
        if (kc + 1 < 8) {
            issue(kc + 1, buf ^ 1);
            cpa_commit();
            cpa_wait<1>();
        } else {
            cpa_wait<0>();
        }
        __syncthreads();

#pragma unroll
        for (int kk = 0; kk < 4; kk++) {
            uint32_t a[2][4];
#pragma unroll
            for (int mt = 0; mt < 2; mt++) {
                int r = wm + mt * 16 + (lane & 7) + ((lane >> 3) & 1) * 8;
                int ch = kk * 2 + (lane >> 4);
                ldm4(asb[buf] + swz(r, ch * 16), a[mt][0], a[mt][1], a[mt][2], a[mt][3]);
            }
            uint32_t b[4][2];
#pragma unroll
            for (int p = 0; p < 2; p++) {
                int r = wn + p * 16 + (lane & 7) + ((lane >> 4) & 1) * 8;
                int ch = kk * 2 + ((lane >> 3) & 1);
                uint32_t r0, r1, r2, r3;
                ldm4(bsb[buf] + swz(r, ch * 16), r0, r1, r2, r3);
                b[p * 2][0] = r0; b[p * 2][1] = r1;
                b[p * 2 + 1][0] = r2; b[p * 2 + 1][1] = r3;
            }
#pragma unroll
            for (int mt = 0; mt < 2; mt++)
#pragma unroll
                for (int nt = 0; nt < 4; nt++)
                    mma_bf16(acc[mt][nt], a[mt][0], a[mt][1], a[mt][2], a[mt][3],
                             b[nt][0], b[nt][1]);
        }
    }

#pragma unroll
    for (int mt = 0; mt < 2; mt++) {
#pragma unroll
        for (int nt = 0; nt < 4; nt++) {
            int n = n0 + wn + nt * 8 + (lane & 3) * 2;
            float b0 = g_bias[n], b1 = g_bias[n + 1];
            int region = n >> 9;            // 0:K  1:Q  2:V
            int col = n & 511;
            int h = col >> 6;
            int d = col & 63;
            __nv_bfloat16* dst = (region == 0) ? g_K : ((region == 1) ? g_Q : g_V);
            float sc = (region == 0) ? CSC : 1.0f;
#pragma unroll
            for (int half = 0; half < 2; half++) {
                int m = m0 + wm + mt * 16 + (lane >> 2) + half * 8;
                int bb = m >> 12;
                int s = m & 4095;
                float v0 = (acc[mt][nt][half * 2 + 0] + b0) * sc;
                float v1 = (acc[mt][nt][half * 2 + 1] + b1) * sc;
                size_t off = ((size_t)(bb * NH + h) * SEQ + s) * DH + d;
                *reinterpret_cast<__nv_bfloat162*>(dst + off) = __floats2bfloat162_rn(v0, v1);
            }
        }
    }
}

// ---------------- attention kernel ----------------
// grid (SEQ/128, BHEADS); 128 threads (4 warps), each warp owns 32 i-rows
// (two 16-row strips sharing every Q/V fragment). 2 CTAs/SM -> 4 warps/SMSP
// for latency hiding at the efficient MMA:ldmatrix ratio. No-max log2-domain
// softmax (p = 2^s directly); l via tensor-core P@ones.
__global__ __launch_bounds__(128, 2) void attn_kernel(const float* __restrict__ mfeat,
                                                      float* __restrict__ out) {
    extern __shared__ char smem[];
    const uint32_t smb = (uint32_t)__cvta_generic_to_shared(smem);
    const uint32_t ksb = smb + KSM_OFF;
    const uint32_t qsb[2] = { smb + QSM_OFF0, smb + QSM_OFF1 };
    const uint32_t vsb[2] = { smb + VSM_OFF0, smb + VSM_OFF1 };

    const int tid = threadIdx.x;
    const int lane = tid & 31;
    const int wid = tid >> 5;      // 0..3
    const int i0 = blockIdx.x * ITILE;
    const int bh = blockIdx.y;

    const __nv_bfloat16* Kg = g_K + (size_t)bh * SEQ * DH;
    const __nv_bfloat16* Qg = g_Q + (size_t)bh * SEQ * DH;
    const __nv_bfloat16* Vg = g_V + (size_t)bh * SEQ * DH;

    // K tile load (128 rows x 8 chunks, resident; fragments hoisted)
#pragma unroll
    for (int i = 0; i < 8; i++) {
        int id = tid + i * 128;
        int r = id >> 3, ch = id & 7;
        cpa16(ksb + swz(r, ch * 16), Kg + (size_t)(i0 + r) * DH + ch * 8);
    }
    cpa_commit();

    auto issue_qv = [&](int jt, int buf) {
        int j0 = jt * JTILE;
#pragma unroll
        for (int i = 0; i < 4; i++) {
            int id = tid + i * 128;
            int r = id >> 3, ch = id & 7;
            cpa16(qsb[buf] + swz(r, ch * 16), Qg + (size_t)(j0 + r) * DH + ch * 8);
            cpa16(vsb[buf] + swz(r, ch * 16), Vg + (size_t)(j0 + r) * DH + ch * 8);
        }
    };

    issue_qv(0, 0);
    cpa_commit();

    // wait for K, hoist K fragments for both strips
    cpa_wait<1>();
    __syncthreads();
    uint32_t kf[2][4][4];
#pragma unroll
    for (int st = 0; st < 2; st++) {
#pragma unroll
        for (int kk = 0; kk < 4; kk++) {
            int r = wid * 32 + st * 16 + (lane & 7) + ((lane >> 3) & 1) * 8;
            int ch = kk * 2 + (lane >> 4);
            ldm4(ksb + swz(r, ch * 16), kf[st][kk][0], kf[st][kk][1], kf[st][kk][2], kf[st][kk][3]);
        }
    }

    const uint32_t ONES2 = 0x3F803F80u;   // bf16x2 {1.0, 1.0}
    float lacc[2][4] = {};                // per-strip row sums via tensor core
    float o[2][8][4] = {};

    const int NT = SEQ / JTILE;
    constexpr int NP = JTILE / 16;        // 16-j blocks per stage

    for (int jt = 0; jt < NT; jt++) {
        const int buf = jt & 1;
        if (jt + 1 < NT) {
            issue_qv(jt + 1, buf ^ 1);
            cpa_commit();
            cpa_wait<1>();
        } else {
            cpa_wait<0>();
        }
        __syncthreads();

        // QK of one 16-j block into s
        auto qk = [&](int p, float (&s)[2][2][4]) {
#pragma unroll
            for (int st = 0; st < 2; st++)
#pragma unroll
                for (int a = 0; a < 2; a++)
#pragma unroll
                    for (int e = 0; e < 4; e++) s[st][a][e] = 0.f;
#pragma unroll
            for (int kk = 0; kk < 4; kk++) {
                int r = p * 16 + (lane & 7) + ((lane >> 4) & 1) * 8;
                int ch = kk * 2 + ((lane >> 3) & 1);
                uint32_t b0, b1, b2, b3;
                ldm4(qsb[buf] + swz(r, ch * 16), b0, b1, b2, b3);
#pragma unroll
                for (int st = 0; st < 2; st++) {
                    mma_bf16(s[st][0], kf[st][kk][0], kf[st][kk][1], kf[st][kk][2], kf[st][kk][3], b0, b1);
                    mma_bf16(s[st][1], kf[st][kk][0], kf[st][kk][1], kf[st][kk][2], kf[st][kk][3], b2, b3);
                }
            }
        };

        float sA[2][2][4], sB[2][2][4];
        qk(0, sA);

#pragma unroll
        for (int p = 0; p < NP; p++) {
            float (&sc)[2][2][4] = (p & 1) ? sB : sA;
            float (&sn)[2][2][4] = (p & 1) ? sA : sB;

            // exp of current block (MUFU; latency hidden by next QK below)
            uint32_t pa[2][4];
#pragma unroll
            for (int st = 0; st < 2; st++) {
                pa[st][0] = ex2bf2_(packbf(sc[st][0][0], sc[st][0][1]));
                pa[st][1] = ex2bf2_(packbf(sc[st][0][2], sc[st][0][3]));
                pa[st][2] = ex2bf2_(packbf(sc[st][1][0], sc[st][1][1]));
                pa[st][3] = ex2bf2_(packbf(sc[st][1][2], sc[st][1][3]));
            }

            // QK of next block — independent MMAs fill the MUFU latency
            if (p + 1 < NP) qk(p + 1, sn);

            // O += P(32x16) @ V_block(16x64)
#pragma unroll
            for (int cb = 0; cb < 8; cb += 2) {
                int r = p * 16 + (lane & 7) + ((lane >> 3) & 1) * 8;
                int ch = cb + (lane >> 4);
                uint32_t b0, b1, b2, b3;
                ldm4t(vsb[buf] + swz(r, ch * 16), b0, b1, b2, b3);
#pragma unroll
                for (int st = 0; st < 2; st++) {
                    mma_bf16(o[st][cb + 0], pa[st][0], pa[st][1], pa[st][2], pa[st][3], b0, b1);
                    mma_bf16(o[st][cb + 1], pa[st][0], pa[st][1], pa[st][2], pa[st][3], b2, b3);
                }
            }

            // l += P @ ones
#pragma unroll
            for (int st = 0; st < 2; st++)
                mma_bf16(lacc[st], pa[st][0], pa[st][1], pa[st][2], pa[st][3], ONES2, ONES2);
        }
        __syncthreads();
    }

    // ---- epilogue: out = m_feats + O / l ----
    const int b = bh >> 3;
    const int h = bh & 7;
#pragma unroll
    for (int st = 0; st < 2; st++) {
        float rl0 = rcpf_(lacc[st][0]);
        float rl1 = rcpf_(lacc[st][2]);
        const int gi0 = i0 + wid * 32 + st * 16 + (lane >> 2);
#pragma unroll
        for (int nt = 0; nt < 8; nt++) {
            int dcol = h * 64 + nt * 8 + (lane & 3) * 2;
            size_t idx0 = ((size_t)(b * SEQ + gi0)) * DMODEL + dcol;
            size_t idx1 = idx0 + (size_t)8 * DMODEL;
            float2 f0 = *reinterpret_cast<const float2*>(mfeat + idx0);
            float2 f1 = *reinterpret_cast<const float2*>(mfeat + idx1);
            float2 w0 = make_float2(f0.x + o[st][nt][0] * rl0, f0.y + o[st][nt][1] * rl0);
            float2 w1 = make_float2(f1.x + o[st][nt][2] * rl1, f1.y + o[st][nt][3] * rl1);
            *reinterpret_cast<float2*>(out + idx0) = w0;
            *reinterpret_cast<float2*>(out + idx1) = w1;
        }
    }
}

// ---------------- launch ----------------
extern "C" void kernel_launch(void* const* d_in, const int* in_sizes, int n_in,
                              void* d_out, int out_size) {
    const float* mf = (const float*)d_in[0];
    const float* Wc = (const float*)d_in[1];
    const float* bc = (const float*)d_in[2];
    const float* Wv = (const float*)d_in[3];
    const float* bv = (const float*)d_in[4];
    float* out = (float*)d_out;

    cudaFuncSetAttribute(attn_kernel, cudaFuncAttributeMaxDynamicSharedMemorySize, SMEM_BYTES);

    cvt_X_kernel<<<MROWS * DMODEL / 1024, 1024>>>(mf);
    cvt_W_kernel<<<NOUT * DMODEL / 1024, 1024>>>(Wc, bc, Wv, bv);
    proj_kernel<<<dim3(MROWS / 128, NOUT / 64), 256>>>();
    attn_kernel<<<dim3(SEQ / ITILE, BHEADS), 128, SMEM_BYTES>>>(mf, out);
}

// round 13
// speedup vs baseline: 1.0399x; 1.0041x over previous
#include <cuda_runtime.h>
#include <cuda_bf16.h>
#include <stdint.h>

#define DINL __device__ __forceinline__

namespace {
constexpr int BATCH  = 2;
constexpr int SEQ    = 4096;
constexpr int DMODEL = 512;
constexpr int NH     = 8;
constexpr int DH     = 64;
constexpr int MROWS  = BATCH * SEQ;   // 8192
constexpr int NOUT   = 3 * DMODEL;    // 1536
constexpr int BHEADS = BATCH * NH;    // 16
constexpr float CSC  = 0.18033688011112042f;  // log2(e) / sqrt(64)

constexpr int ITILE  = 128;           // CTA i-rows (32 per warp, 4 warps)
constexpr int JTILE  = 128;           // j-rows per stage
// attn dynamic smem layout (bytes)
constexpr int KSM_OFF  = 0;                       // 128 * 128B = 16384
constexpr int QSM_OFF0 = 16384;                   // 128 * 128B = 16384
constexpr int QSM_OFF1 = 32768;
constexpr int VSM_OFF0 = 49152;
constexpr int VSM_OFF1 = 65536;
constexpr int SMEM_BYTES = 81920;                 // 80 KB -> 2 CTAs/SM (160 KB)
}

// ---------------- scratch (device globals; no allocation allowed) ----------------
__device__ __nv_bfloat16 g_X[MROWS * DMODEL];
__device__ __nv_bfloat16 g_W[NOUT * DMODEL];     // rows [0,512)=Wv, [512,1536)=Wc
__device__ float         g_bias[NOUT];           // [0,512)=bv, [512,1536)=bc
__device__ __nv_bfloat16 g_K[BHEADS * SEQ * DH]; // pre-scaled by CSC
__device__ __nv_bfloat16 g_Q[BHEADS * SEQ * DH];
__device__ __nv_bfloat16 g_V[BHEADS * SEQ * DH];

// ---------------- helpers ----------------
DINL uint32_t swz(uint32_t r, uint32_t cByte) {
    return r * 128u + (cByte ^ ((r & 7u) << 4));
}

DINL void cpa16(uint32_t dst, const void* src) {
    asm volatile("cp.async.cg.shared.global [%0], [%1], 16;\n" :: "r"(dst), "l"(src));
}
DINL void cpa_commit() { asm volatile("cp.async.commit_group;\n"); }
template <int N> DINL void cpa_wait() { asm volatile("cp.async.wait_group %0;\n" :: "n"(N)); }

DINL void ldm4(uint32_t addr, uint32_t& r0, uint32_t& r1, uint32_t& r2, uint32_t& r3) {
    asm volatile("ldmatrix.sync.aligned.m8n8.x4.shared.b16 {%0,%1,%2,%3}, [%4];"
                 : "=r"(r0), "=r"(r1), "=r"(r2), "=r"(r3) : "r"(addr));
}
DINL void ldm4t(uint32_t addr, uint32_t& r0, uint32_t& r1, uint32_t& r2, uint32_t& r3) {
    asm volatile("ldmatrix.sync.aligned.m8n8.x4.trans.shared.b16 {%0,%1,%2,%3}, [%4];"
                 : "=r"(r0), "=r"(r1), "=r"(r2), "=r"(r3) : "r"(addr));
}

DINL void mma_bf16(float* c, uint32_t a0, uint32_t a1, uint32_t a2, uint32_t a3,
                   uint32_t b0, uint32_t b1) {
    asm volatile(
        "mma.sync.aligned.m16n8k16.row.col.f32.bf16.bf16.f32 "
        "{%0,%1,%2,%3}, {%4,%5,%6,%7}, {%8,%9}, {%0,%1,%2,%3};"
        : "+f"(c[0]), "+f"(c[1]), "+f"(c[2]), "+f"(c[3])
        : "r"(a0), "r"(a1), "r"(a2), "r"(a3), "r"(b0), "r"(b1));
}

DINL float rcpf_(float x) { float y; asm("rcp.approx.f32 %0, %1;" : "=f"(y) : "f"(x)); return y; }

DINL uint32_t packbf(float lo, float hi) {
    __nv_bfloat162 t = __floats2bfloat162_rn(lo, hi);
    return *reinterpret_cast<uint32_t*>(&t);
}

DINL uint32_t ex2bf2_(uint32_t x) {
    uint32_t y;
    asm("ex2.approx.ftz.bf16x2 %0, %1;" : "=r"(y) : "r"(x));
    return y;
}

// ---------------- convert kernels ----------------
__global__ void cvt_X_kernel(const float* __restrict__ x) {
    int i = blockIdx.x * 1024 + threadIdx.x;
    g_X[i] = __float2bfloat16(x[i]);
}

__global__ void cvt_W_kernel(const float* __restrict__ Wc, const float* __restrict__ bc,
                             const float* __restrict__ Wv, const float* __restrict__ bv) {
    int i = blockIdx.x * 1024 + threadIdx.x;
    int row = i >> 9;
    int col = i & 511;
    float v = (row < DMODEL) ? Wv[row * DMODEL + col] : Wc[(row - DMODEL) * DMODEL + col];
    g_W[i] = __float2bfloat16(v);
    if (i < NOUT) g_bias[i] = (i < DMODEL) ? bv[i] : bc[i - DMODEL];
}

// ---------------- projection GEMM: C[8192,1536] = X @ W^T + bias ----------------
// CTA tile 128(M) x 128(N), BK=64, 8 warps (4M x 2N), warp tile 32x64.
// MMA:ldmatrix ratio 16:6 — and half the X re-reads vs the 64-wide N tile.
__global__ __launch_bounds__(256) void proj_kernel() {
    __shared__ __nv_bfloat16 As[2][128 * 64];
    __shared__ __nv_bfloat16 Bs[2][128 * 64];

    const int tid = threadIdx.x;
    const int lane = tid & 31;
    const int wid = tid >> 5;
    const int m0 = blockIdx.x * 128;
    const int n0 = blockIdx.y * 128;
    const int wm = (wid & 3) * 32;
    const int wn = (wid >> 2) * 64;

    uint32_t asb[2], bsb[2];
    asb[0] = (uint32_t)__cvta_generic_to_shared(As[0]);
    asb[1] = (uint32_t)__cvta_generic_to_shared(As[1]);
    bsb[0] = (uint32_t)__cvta_generic_to_shared(Bs[0]);
    bsb[1] = (uint32_t)__cvta_generic_to_shared(Bs[1]);

    auto issue = [&](int kc, int buf) {
        const int k0 = kc * 64;
#pragma unroll
        for (int i = 0; i < 4; i++) {
            int id = tid + i * 256;
            int r = id >> 3, ch = id & 7;
            cpa16(asb[buf] + swz(r, ch * 16), g_X + (size_t)(m0 + r) * DMODEL + k0 + ch * 8);
            cpa16(bsb[buf] + swz(r, ch * 16), g_W + (size_t)(n0 + r) * DMODEL + k0 + ch * 8);
        }
    };

    float acc[2][8][4] = {};

    issue(0, 0);
    cpa_commit();

    for (int kc = 0; kc < 8; kc++) {
        const int buf = kc & 1;
        __syncthreads();
        if (kc + 1 < 8) {
            issue(kc + 1, buf ^ 1);
            cpa_commit();
            cpa_wait<1>();
        } else {
            cpa_wait<0>();
        }
        __syncthreads();

#pragma unroll
        for (int kk = 0; kk < 4; kk++) {
            uint32_t a[2][4];
#pragma unroll
            for (int mt = 0; mt < 2; mt++) {
                int r = wm + mt * 16 + (lane & 7) + ((lane >> 3) & 1) * 8;
                int ch = kk * 2 + (lane >> 4);
                ldm4(asb[buf] + swz(r, ch * 16), a[mt][0], a[mt][1], a[mt][2], a[mt][3]);
            }
            uint32_t b[8][2];
#pragma unroll
            for (int p = 0; p < 4; p++) {
                int r = wn + p * 16 + (lane & 7) + ((lane >> 4) & 1) * 8;
                int ch = kk * 2 + ((lane >> 3) & 1);
                uint32_t r0, r1, r2, r3;
                ldm4(bsb[buf] + swz(r, ch * 16), r0, r1, r2, r3);
                b[p * 2][0] = r0; b[p * 2][1] = r1;
                b[p * 2 + 1][0] = r2; b[p * 2 + 1][1] = r3;
            }
#pragma unroll
            for (int mt = 0; mt < 2; mt++)
#pragma unroll
                for (int nt = 0; nt < 8; nt++)
                    mma_bf16(acc[mt][nt], a[mt][0], a[mt][1], a[mt][2], a[mt][3],
                             b[nt][0], b[nt][1]);
        }
    }

    // epilogue: bias + scatter into per-head layouts (bf16); K gets pre-scaled by CSC
#pragma unroll
    for (int mt = 0; mt < 2; mt++) {
#pragma unroll
        for (int nt = 0; nt < 8; nt++) {
            int n = n0 + wn + nt * 8 + (lane & 3) * 2;
            float b0 = g_bias[n], b1 = g_bias[n + 1];
            int region = n >> 9;            // 0:K  1:Q  2:V
            int col = n & 511;
            int h = col >> 6;
            int d = col & 63;
            __nv_bfloat16* dst = (region == 0) ? g_K : ((region == 1) ? g_Q : g_V);
            float sc = (region == 0) ? CSC : 1.0f;
#pragma unroll
            for (int half = 0; half < 2; half++) {
                int m = m0 + wm + mt * 16 + (lane >> 2) + half * 8;
                int bb = m >> 12;
                int s = m & 4095;
                float v0 = (acc[mt][nt][half * 2 + 0] + b0) * sc;
                float v1 = (acc[mt][nt][half * 2 + 1] + b1) * sc;
                size_t off = ((size_t)(bb * NH + h) * SEQ + s) * DH + d;
                *reinterpret_cast<__nv_bfloat162*>(dst + off) = __floats2bfloat162_rn(v0, v1);
            }
        }
    }
}

// ---------------- attention kernel ----------------
// grid (SEQ/128, BHEADS); 128 threads (4 warps), each warp owns 32 i-rows
// (two 16-row strips sharing every Q/V fragment). 2 CTAs/SM. JTILE=128 to
// halve barrier/loop overhead. No-max log2-domain softmax (p = 2^s directly);
// l via tensor-core P@ones.
__global__ __launch_bounds__(128, 2) void attn_kernel(const float* __restrict__ mfeat,
                                                      float* __restrict__ out) {
    extern __shared__ char smem[];
    const uint32_t smb = (uint32_t)__cvta_generic_to_shared(smem);
    const uint32_t ksb = smb + KSM_OFF;
    const uint32_t qsb[2] = { smb + QSM_OFF0, smb + QSM_OFF1 };
    const uint32_t vsb[2] = { smb + VSM_OFF0, smb + VSM_OFF1 };

    const int tid = threadIdx.x;
    const int lane = tid & 31;
    const int wid = tid >> 5;      // 0..3
    const int i0 = blockIdx.x * ITILE;
    const int bh = blockIdx.y;

    const __nv_bfloat16* Kg = g_K + (size_t)bh * SEQ * DH;
    const __nv_bfloat16* Qg = g_Q + (size_t)bh * SEQ * DH;
    const __nv_bfloat16* Vg = g_V + (size_t)bh * SEQ * DH;

    // K tile load (128 rows x 8 chunks, resident; fragments hoisted)
#pragma unroll
    for (int i = 0; i < 8; i++) {
        int id = tid + i * 128;
        int r = id >> 3, ch = id & 7;
        cpa16(ksb + swz(r, ch * 16), Kg + (size_t)(i0 + r) * DH + ch * 8);
    }
    cpa_commit();

    auto issue_qv = [&](int jt, int buf) {
        int j0 = jt * JTILE;
#pragma unroll
        for (int i = 0; i < 8; i++) {
            int id = tid + i * 128;
            int r = id >> 3, ch = id & 7;
            cpa16(qsb[buf] + swz(r, ch * 16), Qg + (size_t)(j0 + r) * DH + ch * 8);
            cpa16(vsb[buf] + swz(r, ch * 16), Vg + (size_t)(j0 + r) * DH + ch * 8);
        }
    };

    issue_qv(0, 0);
    cpa_commit();

    // wait for K, hoist K fragments for both strips
    cpa_wait<1>();
    __syncthreads();
    uint32_t kf[2][4][4];
#pragma unroll
    for (int st = 0; st < 2; st++) {
#pragma unroll
        for (int kk = 0; kk < 4; kk++) {
            int r = wid * 32 + st * 16 + (lane & 7) + ((lane >> 3) & 1) * 8;
            int ch = kk * 2 + (lane >> 4);
            ldm4(ksb + swz(r, ch * 16), kf[st][kk][0], kf[st][kk][1], kf[st][kk][2], kf[st][kk][3]);
        }
    }

    const uint32_t ONES2 = 0x3F803F80u;   // bf16x2 {1.0, 1.0}
    float lacc[2][4] = {};                // per-strip row sums via tensor core
    float o[2][8][4] = {};

    const int NT = SEQ / JTILE;           // 32
    constexpr int NP = JTILE / 16;        // 8 16-j blocks per stage

    for (int jt = 0; jt < NT; jt++) {
        const int buf = jt & 1;
        if (jt + 1 < NT) {
            issue_qv(jt + 1, buf ^ 1);
            cpa_commit();
            cpa_wait<1>();
        } else {
            cpa_wait<0>();
        }
        __syncthreads();

        // QK of one 16-j block into s
        auto qk = [&](int p, float (&s)[2][2][4]) {
#pragma unroll
            for (int st = 0; st < 2; st++)
#pragma unroll
                for (int a = 0; a < 2; a++)
#pragma unroll
                    for (int e = 0; e < 4; e++) s[st][a][e] = 0.f;
#pragma unroll
            for (int kk = 0; kk < 4; kk++) {
                int r = p * 16 + (lane & 7) + ((lane >> 4) & 1) * 8;
                int ch = kk * 2 + ((lane >> 3) & 1);
                uint32_t b0, b1, b2, b3;
                ldm4(qsb[buf] + swz(r, ch * 16), b0, b1, b2, b3);
#pragma unroll
                for (int st = 0; st < 2; st++) {
                    mma_bf16(s[st][0], kf[st][kk][0], kf[st][kk][1], kf[st][kk][2], kf[st][kk][3], b0, b1);
                    mma_bf16(s[st][1], kf[st][kk][0], kf[st][kk][1], kf[st][kk][2], kf[st][kk][3], b2, b3);
                }
            }
        };

        float sA[2][2][4], sB[2][2][4];
        qk(0, sA);

#pragma unroll
        for (int p = 0; p < NP; p++) {
            float (&sc)[2][2][4] = (p & 1) ? sB : sA;
            float (&sn)[2][2][4] = (p & 1) ? sA : sB;

            // exp of current block (MUFU; latency hidden by next QK below)
            uint32_t pa[2][4];
#pragma unroll
            for (int st = 0; st < 2; st++) {
                pa[st][0] = ex2bf2_(packbf(sc[st][0][0], sc[st][0][1]));
                pa[st][1] = ex2bf2_(packbf(sc[st][0][2], sc[st][0][3]));
                pa[st][2] = ex2bf2_(packbf(sc[st][1][0], sc[st][1][1]));
                pa[st][3] = ex2bf2_(packbf(sc[st][1][2], sc[st][1][3]));
            }

            // QK of next block — independent MMAs fill the MUFU latency
            if (p + 1 < NP) qk(p + 1, sn);

            // O += P(32x16) @ V_block(16x64)
#pragma unroll
            for (int cb = 0; cb < 8; cb += 2) {
                int r = p * 16 + (lane & 7) + ((lane >> 3) & 1) * 8;
                int ch = cb + (lane >> 4);
                uint32_t b0, b1, b2, b3;
                ldm4t(vsb[buf] + swz(r, ch * 16), b0, b1, b2, b3);
#pragma unroll
                for (int st = 0; st < 2; st++) {
                    mma_bf16(o[st][cb + 0], pa[st][0], pa[st][1], pa[st][2], pa[st][3], b0, b1);
                    mma_bf16(o[st][cb + 1], pa[st][0], pa[st][1], pa[st][2], pa[st][3], b2, b3);
                }
            }

            // l += P @ ones
#pragma unroll
            for (int st = 0; st < 2; st++)
                mma_bf16(lacc[st], pa[st][0], pa[st][1], pa[st][2], pa[st][3], ONES2, ONES2);
        }
        __syncthreads();
    }

    // ---- epilogue: out = m_feats + O / l ----
    const int b = bh >> 3;
    const int h = bh & 7;
#pragma unroll
    for (int st = 0; st < 2; st++) {
        float rl0 = rcpf_(lacc[st][0]);
        float rl1 = rcpf_(lacc[st][2]);
        const int gi0 = i0 + wid * 32 + st * 16 + (lane >> 2);
#pragma unroll
        for (int nt = 0; nt < 8; nt++) {
            int dcol = h * 64 + nt * 8 + (lane & 3) * 2;
            size_t idx0 = ((size_t)(b * SEQ + gi0)) * DMODEL + dcol;
            size_t idx1 = idx0 + (size_t)8 * DMODEL;
            float2 f0 = *reinterpret_cast<const float2*>(mfeat + idx0);
            float2 f1 = *reinterpret_cast<const float2*>(mfeat + idx1);
            float2 w0 = make_float2(f0.x + o[st][nt][0] * rl0, f0.y + o[st][nt][1] * rl0);
            float2 w1 = make_float2(f1.x + o[st][nt][2] * rl1, f1.y + o[st][nt][3] * rl1);
            *reinterpret_cast<float2*>(out + idx0) = w0;
            *reinterpret_cast<float2*>(out + idx1) = w1;
        }
    }
}

// ---------------- launch ----------------
extern "C" void kernel_launch(void* const* d_in, const int* in_sizes, int n_in,
                              void* d_out, int out_size) {
    const float* mf = (const float*)d_in[0];
    const float* Wc = (const float*)d_in[1];
    const float* bc = (const float*)d_in[2];
    const float* Wv = (const float*)d_in[3];
    const float* bv = (const float*)d_in[4];
    float* out = (float*)d_out;

    cudaFuncSetAttribute(attn_kernel, cudaFuncAttributeMaxDynamicSharedMemorySize, SMEM_BYTES);

    cvt_X_kernel<<<MROWS * DMODEL / 1024, 1024>>>(mf);
    cvt_W_kernel<<<NOUT * DMODEL / 1024, 1024>>>(Wc, bc, Wv, bv);
    proj_kernel<<<dim3(MROWS / 128, NOUT / 128), 256>>>();
    attn_kernel<<<dim3(SEQ / ITILE, BHEADS), 128, SMEM_BYTES>>>(mf, out);
}

// round 14
// speedup vs baseline: 1.0467x; 1.0066x over previous
#include <cuda_runtime.h>
#include <cuda_bf16.h>
#include <stdint.h>

#define DINL __device__ __forceinline__

namespace {
constexpr int BATCH  = 2;
constexpr int SEQ    = 4096;
constexpr int DMODEL = 512;
constexpr int NH     = 8;
constexpr int DH     = 64;
constexpr int MROWS  = BATCH * SEQ;   // 8192
constexpr int NOUT   = 3 * DMODEL;    // 1536
constexpr int BHEADS = BATCH * NH;    // 16
constexpr float CSC  = 0.18033688011112042f;  // log2(e) / sqrt(64)

constexpr int ITILE  = 128;           // CTA i-rows (32 per warp, 4 warps)
constexpr int JTILE  = 128;           // j-rows per stage
// attn dynamic smem layout (bytes)
constexpr int KSM_OFF  = 0;                       // 128 * 128B = 16384
constexpr int QSM_OFF0 = 16384;                   // 128 * 128B = 16384
constexpr int QSM_OFF1 = 32768;
constexpr int VSM_OFF0 = 49152;
constexpr int VSM_OFF1 = 65536;
constexpr int SMEM_BYTES = 81920;                 // 80 KB -> 2 CTAs/SM (160 KB)
}

// ---------------- scratch (device globals; no allocation allowed) ----------------
__device__ __nv_bfloat16 g_X[MROWS * DMODEL];
__device__ __nv_bfloat16 g_W[NOUT * DMODEL];     // rows [0,512)=Wv, [512,1536)=Wc
__device__ float         g_bias[NOUT];           // [0,512)=bv, [512,1536)=bc
__device__ __nv_bfloat16 g_K[BHEADS * SEQ * DH]; // pre-scaled by CSC
__device__ __nv_bfloat16 g_Q[BHEADS * SEQ * DH];
__device__ __nv_bfloat16 g_V[BHEADS * SEQ * DH];

// ---------------- helpers ----------------
DINL uint32_t swz(uint32_t r, uint32_t cByte) {
    return r * 128u + (cByte ^ ((r & 7u) << 4));
}

DINL void cpa16(uint32_t dst, const void* src) {
    asm volatile("cp.async.cg.shared.global [%0], [%1], 16;\n" :: "r"(dst), "l"(src));
}
DINL void cpa_commit() { asm volatile("cp.async.commit_group;\n"); }
template <int N> DINL void cpa_wait() { asm volatile("cp.async.wait_group %0;\n" :: "n"(N)); }

DINL void ldm4(uint32_t addr, uint32_t& r0, uint32_t& r1, uint32_t& r2, uint32_t& r3) {
    asm volatile("ldmatrix.sync.aligned.m8n8.x4.shared.b16 {%0,%1,%2,%3}, [%4];"
                 : "=r"(r0), "=r"(r1), "=r"(r2), "=r"(r3) : "r"(addr));
}
DINL void ldm4t(uint32_t addr, uint32_t& r0, uint32_t& r1, uint32_t& r2, uint32_t& r3) {
    asm volatile("ldmatrix.sync.aligned.m8n8.x4.trans.shared.b16 {%0,%1,%2,%3}, [%4];"
                 : "=r"(r0), "=r"(r1), "=r"(r2), "=r"(r3) : "r"(addr));
}

DINL void mma_bf16(float* c, uint32_t a0, uint32_t a1, uint32_t a2, uint32_t a3,
                   uint32_t b0, uint32_t b1) {
    asm volatile(
        "mma.sync.aligned.m16n8k16.row.col.f32.bf16.bf16.f32 "
        "{%0,%1,%2,%3}, {%4,%5,%6,%7}, {%8,%9}, {%0,%1,%2,%3};"
        : "+f"(c[0]), "+f"(c[1]), "+f"(c[2]), "+f"(c[3])
        : "r"(a0), "r"(a1), "r"(a2), "r"(a3), "r"(b0), "r"(b1));
}

DINL float rcpf_(float x) { float y; asm("rcp.approx.f32 %0, %1;" : "=f"(y) : "f"(x)); return y; }

DINL uint32_t packbf(float lo, float hi) {
    __nv_bfloat162 t = __floats2bfloat162_rn(lo, hi);
    return *reinterpret_cast<uint32_t*>(&t);
}

DINL uint32_t ex2bf2_(uint32_t x) {
    uint32_t y;
    asm("ex2.approx.ftz.bf16x2 %0, %1;" : "=r"(y) : "r"(x));
    return y;
}

// ---------------- convert kernels ----------------
__global__ void cvt_X_kernel(const float* __restrict__ x) {
    int i = blockIdx.x * 1024 + threadIdx.x;
    g_X[i] = __float2bfloat16(x[i]);
}

__global__ void cvt_W_kernel(const float* __restrict__ Wc, const float* __restrict__ bc,
                             const float* __restrict__ Wv, const float* __restrict__ bv) {
    int i = blockIdx.x * 1024 + threadIdx.x;
    int row = i >> 9;
    int col = i & 511;
    float v = (row < DMODEL) ? Wv[row * DMODEL + col] : Wc[(row - DMODEL) * DMODEL + col];
    g_W[i] = __float2bfloat16(v);
    if (i < NOUT) g_bias[i] = (i < DMODEL) ? bv[i] : bc[i - DMODEL];
}

// ---------------- projection GEMM: C[8192,1536] = X @ W^T + bias ----------------
// CTA tile 128(M) x 64(N), BK=64, 8 warps (4x2), warp tile 32x32.
// (R11 config: 1536 CTAs, 4 CTAs/SM, 2.6 dense waves — measured faster than 128x128.)
__global__ __launch_bounds__(256) void proj_kernel() {
    __shared__ __nv_bfloat16 As[2][128 * 64];
    __shared__ __nv_bfloat16 Bs[2][64 * 64];

    const int tid = threadIdx.x;
    const int lane = tid & 31;
    const int wid = tid >> 5;
    const int m0 = blockIdx.x * 128;
    const int n0 = blockIdx.y * 64;
    const int wm = (wid & 3) * 32;
    const int wn = (wid >> 2) * 32;

    uint32_t asb[2], bsb[2];
    asb[0] = (uint32_t)__cvta_generic_to_shared(As[0]);
    asb[1] = (uint32_t)__cvta_generic_to_shared(As[1]);
    bsb[0] = (uint32_t)__cvta_generic_to_shared(Bs[0]);
    bsb[1] = (uint32_t)__cvta_generic_to_shared(Bs[1]);

    auto issue = [&](int kc, int buf) {
        const int k0 = kc * 64;
#pragma unroll
        for (int i = 0; i < 4; i++) {
            int id = tid + i * 256;
            int r = id >> 3, ch = id & 7;
            cpa16(asb[buf] + swz(r, ch * 16), g_X + (size_t)(m0 + r) * DMODEL + k0 + ch * 8);
        }
#pragma unroll
        for (int i = 0; i < 2; i++) {
            int id = tid + i * 256;
            int r = id >> 3, ch = id & 7;
            cpa16(bsb[buf] + swz(r, ch * 16), g_W + (size_t)(n0 + r) * DMODEL + k0 + ch * 8);
        }
    };

    float acc[2][4][4] = {};

    issue(0, 0);
    cpa_commit();

    for (int kc = 0; kc < 8; kc++) {
        const int buf = kc & 1;
        __syncthreads();
        if (kc + 1 < 8) {
            issue(kc + 1, buf ^ 1);
            cpa_commit();
            cpa_wait<1>();
        } else {
            cpa_wait<0>();
        }
        __syncthreads();

#pragma unroll
        for (int kk = 0; kk < 4; kk++) {
            uint32_t a[2][4];
#pragma unroll
            for (int mt = 0; mt < 2; mt++) {
                int r = wm + mt * 16 + (lane & 7) + ((lane >> 3) & 1) * 8;
                int ch = kk * 2 + (lane >> 4);
                ldm4(asb[buf] + swz(r, ch * 16), a[mt][0], a[mt][1], a[mt][2], a[mt][3]);
            }
            uint32_t b[4][2];
#pragma unroll
            for (int p = 0; p < 2; p++) {
                int r = wn + p * 16 + (lane & 7) + ((lane >> 4) & 1) * 8;
                int ch = kk * 2 + ((lane >> 3) & 1);
                uint32_t r0, r1, r2, r3;
                ldm4(bsb[buf] + swz(r, ch * 16), r0, r1, r2, r3);
                b[p * 2][0] = r0; b[p * 2][1] = r1;
                b[p * 2 + 1][0] = r2; b[p * 2 + 1][1] = r3;
            }
#pragma unroll
            for (int mt = 0; mt < 2; mt++)
#pragma unroll
                for (int nt = 0; nt < 4; nt++)
                    mma_bf16(acc[mt][nt], a[mt][0], a[mt][1], a[mt][2], a[mt][3],
                             b[nt][0], b[nt][1]);
        }
    }

    // epilogue: bias + scatter into per-head layouts (bf16); K gets pre-scaled by CSC
#pragma unroll
    for (int mt = 0; mt < 2; mt++) {
#pragma unroll
        for (int nt = 0; nt < 4; nt++) {
            int n = n0 + wn + nt * 8 + (lane & 3) * 2;
            float b0 = g_bias[n], b1 = g_bias[n + 1];
            int region = n >> 9;            // 0:K  1:Q  2:V
            int col = n & 511;
            int h = col >> 6;
            int d = col & 63;
            __nv_bfloat16* dst = (region == 0) ? g_K : ((region == 1) ? g_Q : g_V);
            float sc = (region == 0) ? CSC : 1.0f;
#pragma unroll
            for (int half = 0; half < 2; half++) {
                int m = m0 + wm + mt * 16 + (lane >> 2) + half * 8;
                int bb = m >> 12;
                int s = m & 4095;
                float v0 = (acc[mt][nt][half * 2 + 0] + b0) * sc;
                float v1 = (acc[mt][nt][half * 2 + 1] + b1) * sc;
                size_t off = ((size_t)(bb * NH + h) * SEQ + s) * DH + d;
                *reinterpret_cast<__nv_bfloat162*>(dst + off) = __floats2bfloat162_rn(v0, v1);
            }
        }
    }
}

// ---------------- attention kernel ----------------
// grid (SEQ/128, BHEADS); 128 threads (4 warps), each warp owns 32 i-rows
// (two 16-row strips sharing every Q/V fragment). 2 CTAs/SM. JTILE=128.
// Sequential per-16j-block: QK -> exp -> PV (pipelining measured neutral;
// removing it relieves the 255-reg cap). No-max log2-domain softmax;
// l via tensor-core P@ones.
__global__ __launch_bounds__(128, 2) void attn_kernel(const float* __restrict__ mfeat,
                                                      float* __restrict__ out) {
    extern __shared__ char smem[];
    const uint32_t smb = (uint32_t)__cvta_generic_to_shared(smem);
    const uint32_t ksb = smb + KSM_OFF;
    const uint32_t qsb[2] = { smb + QSM_OFF0, smb + QSM_OFF1 };
    const uint32_t vsb[2] = { smb + VSM_OFF0, smb + VSM_OFF1 };

    const int tid = threadIdx.x;
    const int lane = tid & 31;
    const int wid = tid >> 5;      // 0..3
    const int i0 = blockIdx.x * ITILE;
    const int bh = blockIdx.y;

    const __nv_bfloat16* Kg = g_K + (size_t)bh * SEQ * DH;
    const __nv_bfloat16* Qg = g_Q + (size_t)bh * SEQ * DH;
    const __nv_bfloat16* Vg = g_V + (size_t)bh * SEQ * DH;

    // K tile load (128 rows x 8 chunks, resident; fragments hoisted)
#pragma unroll
    for (int i = 0; i < 8; i++) {
        int id = tid + i * 128;
        int r = id >> 3, ch = id & 7;
        cpa16(ksb + swz(r, ch * 16), Kg + (size_t)(i0 + r) * DH + ch * 8);
    }
    cpa_commit();

    auto issue_qv = [&](int jt, int buf) {
        int j0 = jt * JTILE;
#pragma unroll
        for (int i = 0; i < 8; i++) {
            int id = tid + i * 128;
            int r = id >> 3, ch = id & 7;
            cpa16(qsb[buf] + swz(r, ch * 16), Qg + (size_t)(j0 + r) * DH + ch * 8);
            cpa16(vsb[buf] + swz(r, ch * 16), Vg + (size_t)(j0 + r) * DH + ch * 8);
        }
    };

    issue_qv(0, 0);
    cpa_commit();

    // wait for K, hoist K fragments for both strips
    cpa_wait<1>();
    __syncthreads();
    uint32_t kf[2][4][4];
#pragma unroll
    for (int st = 0; st < 2; st++) {
#pragma unroll
        for (int kk = 0; kk < 4; kk++) {
            int r = wid * 32 + st * 16 + (lane & 7) + ((lane >> 3) & 1) * 8;
            int ch = kk * 2 + (lane >> 4);
            ldm4(ksb + swz(r, ch * 16), kf[st][kk][0], kf[st][kk][1], kf[st][kk][2], kf[st][kk][3]);
        }
    }

    const uint32_t ONES2 = 0x3F803F80u;   // bf16x2 {1.0, 1.0}
    float lacc[2][4] = {};                // per-strip row sums via tensor core
    float o[2][8][4] = {};

    const int NT = SEQ / JTILE;           // 32
    constexpr int NP = JTILE / 16;        // 8 16-j blocks per stage

    for (int jt = 0; jt < NT; jt++) {
        const int buf = jt & 1;
        if (jt + 1 < NT) {
            issue_qv(jt + 1, buf ^ 1);
            cpa_commit();
            cpa_wait<1>();
        } else {
            cpa_wait<0>();
        }
        __syncthreads();

#pragma unroll
        for (int p = 0; p < NP; p++) {
            // ---- S(32x16) = K strips @ Q_block^T ----
            float s[2][2][4] = {};
#pragma unroll
            for (int kk = 0; kk < 4; kk++) {
                int r = p * 16 + (lane & 7) + ((lane >> 4) & 1) * 8;
                int ch = kk * 2 + ((lane >> 3) & 1);
                uint32_t b0, b1, b2, b3;
                ldm4(qsb[buf] + swz(r, ch * 16), b0, b1, b2, b3);
#pragma unroll
                for (int st = 0; st < 2; st++) {
                    mma_bf16(s[st][0], kf[st][kk][0], kf[st][kk][1], kf[st][kk][2], kf[st][kk][3], b0, b1);
                    mma_bf16(s[st][1], kf[st][kk][0], kf[st][kk][1], kf[st][kk][2], kf[st][kk][3], b2, b3);
                }
            }

            // ---- P = 2^S (bf16x2 MUFU) ----
            uint32_t pa[2][4];
#pragma unroll
            for (int st = 0; st < 2; st++) {
                pa[st][0] = ex2bf2_(packbf(s[st][0][0], s[st][0][1]));
                pa[st][1] = ex2bf2_(packbf(s[st][0][2], s[st][0][3]));
                pa[st][2] = ex2bf2_(packbf(s[st][1][0], s[st][1][1]));
                pa[st][3] = ex2bf2_(packbf(s[st][1][2], s[st][1][3]));
            }

            // ---- O += P(32x16) @ V_block(16x64) ----
#pragma unroll
            for (int cb = 0; cb < 8; cb += 2) {
                int r = p * 16 + (lane & 7) + ((lane >> 3) & 1) * 8;
                int ch = cb + (lane >> 4);
                uint32_t b0, b1, b2, b3;
                ldm4t(vsb[buf] + swz(r, ch * 16), b0, b1, b2, b3);
#pragma unroll
                for (int st = 0; st < 2; st++) {
                    mma_bf16(o[st][cb + 0], pa[st][0], pa[st][1], pa[st][2], pa[st][3], b0, b1);
                    mma_bf16(o[st][cb + 1], pa[st][0], pa[st][1], pa[st][2], pa[st][3], b2, b3);
                }
            }

            // ---- l += P @ ones ----
#pragma unroll
            for (int st = 0; st < 2; st++)
                mma_bf16(lacc[st], pa[st][0], pa[st][1], pa[st][2], pa[st][3], ONES2, ONES2);
        }
        __syncthreads();
    }

    // ---- epilogue: out = m_feats + O / l ----
    const int b = bh >> 3;
    const int h = bh & 7;
#pragma unroll
    for (int st = 0; st < 2; st++) {
        float rl0 = rcpf_(lacc[st][0]);
        float rl1 = rcpf_(lacc[st][2]);
        const int gi0 = i0 + wid * 32 + st * 16 + (lane >> 2);
#pragma unroll
        for (int nt = 0; nt < 8; nt++) {
            int dcol = h * 64 + nt * 8 + (lane & 3) * 2;
            size_t idx0 = ((size_t)(b * SEQ + gi0)) * DMODEL + dcol;
            size_t idx1 = idx0 + (size_t)8 * DMODEL;
            float2 f0 = *reinterpret_cast<const float2*>(mfeat + idx0);
            float2 f1 = *reinterpret_cast<const float2*>(mfeat + idx1);
            float2 w0 = make_float2(f0.x + o[st][nt][0] * rl0, f0.y + o[st][nt][1] * rl0);
            float2 w1 = make_float2(f1.x + o[st][nt][2] * rl1, f1.y + o[st][nt][3] * rl1);
            *reinterpret_cast<float2*>(out + idx0) = w0;
            *reinterpret_cast<float2*>(out + idx1) = w1;
        }
    }
}

// ---------------- launch ----------------
extern "C" void kernel_launch(void* const* d_in, const int* in_sizes, int n_in,
                              void* d_out, int out_size) {
    const float* mf = (const float*)d_in[0];
    const float* Wc = (const float*)d_in[1];
    const float* bc = (const float*)d_in[2];
    const float* Wv = (const float*)d_in[3];
    const float* bv = (const float*)d_in[4];
    float* out = (float*)d_out;

    cudaFuncSetAttribute(attn_kernel, cudaFuncAttributeMaxDynamicSharedMemorySize, SMEM_BYTES);

    cvt_X_kernel<<<MROWS * DMODEL / 1024, 1024>>>(mf);
    cvt_W_kernel<<<NOUT * DMODEL / 1024, 1024>>>(Wc, bc, Wv, bv);
    proj_kernel<<<dim3(MROWS / 128, NOUT / 64), 256>>>();
    attn_kernel<<<dim3(SEQ / ITILE, BHEADS), 128, SMEM_BYTES>>>(mf, out);
}

// round 15
// speedup vs baseline: 1.0469x; 1.0001x over previous
#include <cuda_runtime.h>
#include <cuda_bf16.h>
#include <stdint.h>

#define DINL __device__ __forceinline__

namespace {
constexpr int BATCH  = 2;
constexpr int SEQ    = 4096;
constexpr int DMODEL = 512;
constexpr int NH     = 8;
constexpr int DH     = 64;
constexpr int MROWS  = BATCH * SEQ;   // 8192
constexpr int NOUT   = 3 * DMODEL;    // 1536
constexpr int BHEADS = BATCH * NH;    // 16
constexpr float CSC  = 0.18033688011112042f;  // log2(e) / sqrt(64)

constexpr int ITILE  = 128;           // CTA i-rows (32 per warp, 4 warps)
constexpr int JTILE  = 128;           // j-rows per stage
// attn dynamic smem layout (bytes)
constexpr int KSM_OFF  = 0;                       // 128 * 128B = 16384
constexpr int QSM_OFF0 = 16384;                   // 128 * 128B = 16384
constexpr int QSM_OFF1 = 32768;
constexpr int VSM_OFF0 = 49152;
constexpr int VSM_OFF1 = 65536;
constexpr int SMEM_BYTES = 81920;                 // 80 KB -> 2 CTAs/SM (160 KB)

constexpr int XELEMS = MROWS * DMODEL;            // 4194304
constexpr int WELEMS = NOUT * DMODEL;             // 786432
}

// ---------------- scratch (device globals; no allocation allowed) ----------------
__device__ __nv_bfloat16 g_X[MROWS * DMODEL];
__device__ __nv_bfloat16 g_W[NOUT * DMODEL];     // rows [0,512)=Wv, [512,1536)=Wc
__device__ float         g_bias[NOUT];           // [0,512)=bv, [512,1536)=bc
__device__ __nv_bfloat16 g_K[BHEADS * SEQ * DH]; // pre-scaled by CSC
__device__ __nv_bfloat16 g_Q[BHEADS * SEQ * DH];
__device__ __nv_bfloat16 g_V[BHEADS * SEQ * DH];

// ---------------- helpers ----------------
DINL uint32_t swz(uint32_t r, uint32_t cByte) {
    return r * 128u + (cByte ^ ((r & 7u) << 4));
}

DINL void cpa16(uint32_t dst, const void* src) {
    asm volatile("cp.async.cg.shared.global [%0], [%1], 16;\n" :: "r"(dst), "l"(src));
}
DINL void cpa_commit() { asm volatile("cp.async.commit_group;\n"); }
template <int N> DINL void cpa_wait() { asm volatile("cp.async.wait_group %0;\n" :: "n"(N)); }

DINL void ldm4(uint32_t addr, uint32_t& r0, uint32_t& r1, uint32_t& r2, uint32_t& r3) {
    asm volatile("ldmatrix.sync.aligned.m8n8.x4.shared.b16 {%0,%1,%2,%3}, [%4];"
                 : "=r"(r0), "=r"(r1), "=r"(r2), "=r"(r3) : "r"(addr));
}
DINL void ldm4t(uint32_t addr, uint32_t& r0, uint32_t& r1, uint32_t& r2, uint32_t& r3) {
    asm volatile("ldmatrix.sync.aligned.m8n8.x4.trans.shared.b16 {%0,%1,%2,%3}, [%4];"
                 : "=r"(r0), "=r"(r1), "=r"(r2), "=r"(r3) : "r"(addr));
}

// accumulate in place: D == C
DINL void mma_bf16(float* c, uint32_t a0, uint32_t a1, uint32_t a2, uint32_t a3,
                   uint32_t b0, uint32_t b1) {
    asm volatile(
        "mma.sync.aligned.m16n8k16.row.col.f32.bf16.bf16.f32 "
        "{%0,%1,%2,%3}, {%4,%5,%6,%7}, {%8,%9}, {%0,%1,%2,%3};"
        : "+f"(c[0]), "+f"(c[1]), "+f"(c[2]), "+f"(c[3])
        : "r"(a0), "r"(a1), "r"(a2), "r"(a3), "r"(b0), "r"(b1));
}

// D = A*B + Z where Z is a persistent zero quad (D != C) — kills per-block zero-init MOVs
DINL void mma_bf16_z(float* d, const float* z,
                     uint32_t a0, uint32_t a1, uint32_t a2, uint32_t a3,
                     uint32_t b0, uint32_t b1) {
    asm volatile(
        "mma.sync.aligned.m16n8k16.row.col.f32.bf16.bf16.f32 "
        "{%0,%1,%2,%3}, {%4,%5,%6,%7}, {%8,%9}, {%10,%11,%12,%13};"
        : "=f"(d[0]), "=f"(d[1]), "=f"(d[2]), "=f"(d[3])
        : "r"(a0), "r"(a1), "r"(a2), "r"(a3), "r"(b0), "r"(b1),
          "f"(z[0]), "f"(z[1]), "f"(z[2]), "f"(z[3]));
}

DINL float rcpf_(float x) { float y; asm("rcp.approx.f32 %0, %1;" : "=f"(y) : "f"(x)); return y; }

DINL uint32_t packbf(float lo, float hi) {
    __nv_bfloat162 t = __floats2bfloat162_rn(lo, hi);
    return *reinterpret_cast<uint32_t*>(&t);
}

DINL uint32_t ex2bf2_(uint32_t x) {
    uint32_t y;
    asm("ex2.approx.ftz.bf16x2 %0, %1;" : "=r"(y) : "r"(x));
    return y;
}

// ---------------- merged convert kernel ----------------
__global__ void cvt_all_kernel(const float* __restrict__ x,
                               const float* __restrict__ Wc, const float* __restrict__ bc,
                               const float* __restrict__ Wv, const float* __restrict__ bv) {
    int i = blockIdx.x * 1024 + threadIdx.x;
    if (i < XELEMS) {
        g_X[i] = __float2bfloat16(x[i]);
    } else {
        int j = i - XELEMS;               // < WELEMS
        int row = j >> 9;
        int col = j & 511;
        float v = (row < DMODEL) ? Wv[row * DMODEL + col] : Wc[(row - DMODEL) * DMODEL + col];
        g_W[j] = __float2bfloat16(v);
        if (j < NOUT) g_bias[j] = (j < DMODEL) ? bv[j] : bc[j - DMODEL];
    }
}

// ---------------- projection GEMM: C[8192,1536] = X @ W^T + bias ----------------
// CTA tile 128(M) x 64(N), BK=64, 8 warps (4x2), warp tile 32x32. (Measured-best config.)
__global__ __launch_bounds__(256) void proj_kernel() {
    __shared__ __nv_bfloat16 As[2][128 * 64];
    __shared__ __nv_bfloat16 Bs[2][64 * 64];

    const int tid = threadIdx.x;
    const int lane = tid & 31;
    const int wid = tid >> 5;
    const int m0 = blockIdx.x * 128;
    const int n0 = blockIdx.y * 64;
    const int wm = (wid & 3) * 32;
    const int wn = (wid >> 2) * 32;

    uint32_t asb[2], bsb[2];
    asb[0] = (uint32_t)__cvta_generic_to_shared(As[0]);
    asb[1] = (uint32_t)__cvta_generic_to_shared(As[1]);
    bsb[0] = (uint32_t)__cvta_generic_to_shared(Bs[0]);
    bsb[1] = (uint32_t)__cvta_generic_to_shared(Bs[1]);

    auto issue = [&](int kc, int buf) {
        const int k0 = kc * 64;
#pragma unroll
        for (int i = 0; i < 4; i++) {
            int id = tid + i * 256;
            int r = id >> 3, ch = id & 7;
            cpa16(asb[buf] + swz(r, ch * 16), g_X + (size_t)(m0 + r) * DMODEL + k0 + ch * 8);
        }
#pragma unroll
        for (int i = 0; i < 2; i++) {
            int id = tid + i * 256;
            int r = id >> 3, ch = id & 7;
            cpa16(bsb[buf] + swz(r, ch * 16), g_W + (size_t)(n0 + r) * DMODEL + k0 + ch * 8);
        }
    };

    float acc[2][4][4] = {};

    issue(0, 0);
    cpa_commit();

    for (int kc = 0; kc < 8; kc++) {
        const int buf = kc & 1;
        __syncthreads();
        if (kc + 1 < 8) {
            issue(kc + 1, buf ^ 1);
            cpa_commit();
            cpa_wait<1>();
        } else {
            cpa_wait<0>();
        }
        __syncthreads();

#pragma unroll
        for (int kk = 0; kk < 4; kk++) {
            uint32_t a[2][4];
#pragma unroll
            for (int mt = 0; mt < 2; mt++) {
                int r = wm + mt * 16 + (lane & 7) + ((lane >> 3) & 1) * 8;
                int ch = kk * 2 + (lane >> 4);
                ldm4(asb[buf] + swz(r, ch * 16), a[mt][0], a[mt][1], a[mt][2], a[mt][3]);
            }
            uint32_t b[4][2];
#pragma unroll
            for (int p = 0; p < 2; p++) {
                int r = wn + p * 16 + (lane & 7) + ((lane >> 4) & 1) * 8;
                int ch = kk * 2 + ((lane >> 3) & 1);
                uint32_t r0, r1, r2, r3;
                ldm4(bsb[buf] + swz(r, ch * 16), r0, r1, r2, r3);
                b[p * 2][0] = r0; b[p * 2][1] = r1;
                b[p * 2 + 1][0] = r2; b[p * 2 + 1][1] = r3;
            }
#pragma unroll
            for (int mt = 0; mt < 2; mt++)
#pragma unroll
                for (int nt = 0; nt < 4; nt++)
                    mma_bf16(acc[mt][nt], a[mt][0], a[mt][1], a[mt][2], a[mt][3],
                             b[nt][0], b[nt][1]);
        }
    }

    // epilogue: bias + scatter into per-head layouts (bf16); K gets pre-scaled by CSC
#pragma unroll
    for (int mt = 0; mt < 2; mt++) {
#pragma unroll
        for (int nt = 0; nt < 4; nt++) {
            int n = n0 + wn + nt * 8 + (lane & 3) * 2;
            float b0 = g_bias[n], b1 = g_bias[n + 1];
            int region = n >> 9;            // 0:K  1:Q  2:V
            int col = n & 511;
            int h = col >> 6;
            int d = col & 63;
            __nv_bfloat16* dst = (region == 0) ? g_K : ((region == 1) ? g_Q : g_V);
            float sc = (region == 0) ? CSC : 1.0f;
#pragma unroll
            for (int half = 0; half < 2; half++) {
                int m = m0 + wm + mt * 16 + (lane >> 2) + half * 8;
                int bb = m >> 12;
                int s = m & 4095;
                float v0 = (acc[mt][nt][half * 2 + 0] + b0) * sc;
                float v1 = (acc[mt][nt][half * 2 + 1] + b1) * sc;
                size_t off = ((size_t)(bb * NH + h) * SEQ + s) * DH + d;
                *reinterpret_cast<__nv_bfloat162*>(dst + off) = __floats2bfloat162_rn(v0, v1);
            }
        }
    }
}

// ---------------- attention kernel ----------------
// grid (SEQ/128, BHEADS); 128 threads (4 warps), each warp owns 32 i-rows
// (two 16-row strips sharing every Q/V fragment). 2 CTAs/SM. JTILE=128.
// QK first k-chunk writes D directly from a persistent zero quad (no per-block
// accumulator zero-init). No-max log2-domain softmax; l via tensor-core P@ones.
__global__ __launch_bounds__(128, 2) void attn_kernel(const float* __restrict__ mfeat,
                                                      float* __restrict__ out) {
    extern __shared__ char smem[];
    const uint32_t smb = (uint32_t)__cvta_generic_to_shared(smem);
    const uint32_t ksb = smb + KSM_OFF;
    const uint32_t qsb[2] = { smb + QSM_OFF0, smb + QSM_OFF1 };
    const uint32_t vsb[2] = { smb + VSM_OFF0, smb + VSM_OFF1 };

    const int tid = threadIdx.x;
    const int lane = tid & 31;
    const int wid = tid >> 5;      // 0..3
    const int i0 = blockIdx.x * ITILE;
    const int bh = blockIdx.y;

    const __nv_bfloat16* Kg = g_K + (size_t)bh * SEQ * DH;
    const __nv_bfloat16* Qg = g_Q + (size_t)bh * SEQ * DH;
    const __nv_bfloat16* Vg = g_V + (size_t)bh * SEQ * DH;

    // K tile load (128 rows x 8 chunks, resident; fragments hoisted)
#pragma unroll
    for (int i = 0; i < 8; i++) {
        int id = tid + i * 128;
        int r = id >> 3, ch = id & 7;
        cpa16(ksb + swz(r, ch * 16), Kg + (size_t)(i0 + r) * DH + ch * 8);
    }
    cpa_commit();

    auto issue_qv = [&](int jt, int buf) {
        int j0 = jt * JTILE;
#pragma unroll
        for (int i = 0; i < 8; i++) {
            int id = tid + i * 128;
            int r = id >> 3, ch = id & 7;
            cpa16(qsb[buf] + swz(r, ch * 16), Qg + (size_t)(j0 + r) * DH + ch * 8);
            cpa16(vsb[buf] + swz(r, ch * 16), Vg + (size_t)(j0 + r) * DH + ch * 8);
        }
    };

    issue_qv(0, 0);
    cpa_commit();

    // wait for K, hoist K fragments for both strips
    cpa_wait<1>();
    __syncthreads();
    uint32_t kf[2][4][4];
#pragma unroll
    for (int st = 0; st < 2; st++) {
#pragma unroll
        for (int kk = 0; kk < 4; kk++) {
            int r = wid * 32 + st * 16 + (lane & 7) + ((lane >> 3) & 1) * 8;
            int ch = kk * 2 + (lane >> 4);
            ldm4(ksb + swz(r, ch * 16), kf[st][kk][0], kf[st][kk][1], kf[st][kk][2], kf[st][kk][3]);
        }
    }

    const uint32_t ONES2 = 0x3F803F80u;   // bf16x2 {1.0, 1.0}
    float zq[4] = {0.f, 0.f, 0.f, 0.f};   // persistent zero quad (C for first QK MMA)
    float lacc[2][4] = {};                // per-strip row sums via tensor core
    float o[2][8][4] = {};

    const int NT = SEQ / JTILE;           // 32
    constexpr int NP = JTILE / 16;        // 8 16-j blocks per stage

    for (int jt = 0; jt < NT; jt++) {
        const int buf = jt & 1;
        if (jt + 1 < NT) {
            issue_qv(jt + 1, buf ^ 1);
            cpa_commit();
            cpa_wait<1>();
        } else {
            cpa_wait<0>();
        }
        __syncthreads();

#pragma unroll
        for (int p = 0; p < NP; p++) {
            // ---- S(32x16) = K strips @ Q_block^T ----
            float s[2][2][4];
#pragma unroll
            for (int kk = 0; kk < 4; kk++) {
                int r = p * 16 + (lane & 7) + ((lane >> 4) & 1) * 8;
                int ch = kk * 2 + ((lane >> 3) & 1);
                uint32_t b0, b1, b2, b3;
                ldm4(qsb[buf] + swz(r, ch * 16), b0, b1, b2, b3);
                if (kk == 0) {
#pragma unroll
                    for (int st = 0; st < 2; st++) {
                        mma_bf16_z(s[st][0], zq, kf[st][0][0], kf[st][0][1], kf[st][0][2], kf[st][0][3], b0, b1);
                        mma_bf16_z(s[st][1], zq, kf[st][0][0], kf[st][0][1], kf[st][0][2], kf[st][0][3], b2, b3);
                    }
                } else {
#pragma unroll
                    for (int st = 0; st < 2; st++) {
                        mma_bf16(s[st][0], kf[st][kk][0], kf[st][kk][1], kf[st][kk][2], kf[st][kk][3], b0, b1);
                        mma_bf16(s[st][1], kf[st][kk][0], kf[st][kk][1], kf[st][kk][2], kf[st][kk][3], b2, b3);
                    }
                }
            }

            // ---- P = 2^S (bf16x2 MUFU) ----
            uint32_t pa[2][4];
#pragma unroll
            for (int st = 0; st < 2; st++) {
                pa[st][0] = ex2bf2_(packbf(s[st][0][0], s[st][0][1]));
                pa[st][1] = ex2bf2_(packbf(s[st][0][2], s[st][0][3]));
                pa[st][2] = ex2bf2_(packbf(s[st][1][0], s[st][1][1]));
                pa[st][3] = ex2bf2_(packbf(s[st][1][2], s[st][1][3]));
            }

            // ---- O += P(32x16) @ V_block(16x64) ----
#pragma unroll
            for (int cb = 0; cb < 8; cb += 2) {
                int r = p * 16 + (lane & 7) + ((lane >> 3) & 1) * 8;
                int ch = cb + (lane >> 4);
                uint32_t b0, b1, b2, b3;
                ldm4t(vsb[buf] + swz(r, ch * 16), b0, b1, b2, b3);
#pragma unroll
                for (int st = 0; st < 2; st++) {
                    mma_bf16(o[st][cb + 0], pa[st][0], pa[st][1], pa[st][2], pa[st][3], b0, b1);
                    mma_bf16(o[st][cb + 1], pa[st][0], pa[st][1], pa[st][2], pa[st][3], b2, b3);
                }
            }

            // ---- l += P @ ones ----
#pragma unroll
            for (int st = 0; st < 2; st++)
                mma_bf16(lacc[st], pa[st][0], pa[st][1], pa[st][2], pa[st][3], ONES2, ONES2);
        }
        __syncthreads();
    }

    // ---- epilogue: out = m_feats + O / l ----
    const int b = bh >> 3;
    const int h = bh & 7;
#pragma unroll
    for (int st = 0; st < 2; st++) {
        float rl0 = rcpf_(lacc[st][0]);
        float rl1 = rcpf_(lacc[st][2]);
        const int gi0 = i0 + wid * 32 + st * 16 + (lane >> 2);
#pragma unroll
        for (int nt = 0; nt < 8; nt++) {
            int dcol = h * 64 + nt * 8 + (lane & 3) * 2;
            size_t idx0 = ((size_t)(b * SEQ + gi0)) * DMODEL + dcol;
            size_t idx1 = idx0 + (size_t)8 * DMODEL;
            float2 f0 = *reinterpret_cast<const float2*>(mfeat + idx0);
            float2 f1 = *reinterpret_cast<const float2*>(mfeat + idx1);
            float2 w0 = make_float2(f0.x + o[st][nt][0] * rl0, f0.y + o[st][nt][1] * rl0);
            float2 w1 = make_float2(f1.x + o[st][nt][2] * rl1, f1.y + o[st][nt][3] * rl1);
            *reinterpret_cast<float2*>(out + idx0) = w0;
            *reinterpret_cast<float2*>(out + idx1) = w1;
        }
    }
}

// ---------------- launch ----------------
extern "C" void kernel_launch(void* const* d_in, const int* in_sizes, int n_in,
                              void* d_out, int out_size) {
    const float* mf = (const float*)d_in[0];
    const float* Wc = (const float*)d_in[1];
    const float* bc = (const float*)d_in[2];
    const float* Wv = (const float*)d_in[3];
    const float* bv = (const float*)d_in[4];
    float* out = (float*)d_out;

    cudaFuncSetAttribute(attn_kernel, cudaFuncAttributeMaxDynamicSharedMemorySize, SMEM_BYTES);

    cvt_all_kernel<<<(XELEMS + WELEMS) / 1024, 1024>>>(mf, Wc, bc, Wv, bv);
    proj_kernel<<<dim3(MROWS / 128, NOUT / 64), 256>>>();
    attn_kernel<<<dim3(SEQ / ITILE, BHEADS), 128, SMEM_BYTES>>>(mf, out);
}

// round 16
// speedup vs baseline: 1.0829x; 1.0344x over previous
#include <cuda_runtime.h>
#include <cuda_bf16.h>
#include <stdint.h>

#define DINL __device__ __forceinline__

namespace {
constexpr int BATCH  = 2;
constexpr int SEQ    = 4096;
constexpr int DMODEL = 512;
constexpr int NH     = 8;
constexpr int DH     = 64;
constexpr int MROWS  = BATCH * SEQ;   // 8192
constexpr int NOUT   = 3 * DMODEL;    // 1536
constexpr int BHEADS = BATCH * NH;    // 16
constexpr float CSC  = 0.18033688011112042f;  // log2(e) / sqrt(64)

constexpr int ITILE  = 128;           // CTA i-rows (32 per warp, 4 warps)
constexpr int JTILE  = 128;           // j-rows per stage
// attn dynamic smem layout (bytes)
constexpr int KSM_OFF  = 0;                       // 128 * 128B = 16384
constexpr int QSM_OFF0 = 16384;                   // 128 * 128B = 16384
constexpr int QSM_OFF1 = 32768;
constexpr int VSM_OFF0 = 49152;
constexpr int VSM_OFF1 = 65536;
constexpr int SMEM_BYTES = 81920;                 // 80 KB -> 2 CTAs/SM (160 KB)

constexpr int XELEMS = MROWS * DMODEL;            // 4194304
constexpr int WELEMS = NOUT * DMODEL;             // 786432
constexpr int XV = XELEMS / 8;                    // 524288 vec8 units
constexpr int WV = WELEMS / 8;                    // 98304
}

// ---------------- scratch (device globals; no allocation allowed) ----------------
__device__ __nv_bfloat16 g_X[MROWS * DMODEL];
__device__ __nv_bfloat16 g_W[NOUT * DMODEL];     // rows [0,512)=Wv, [512,1536)=Wc
__device__ float         g_bias[NOUT];           // [0,512)=bv, [512,1536)=bc
__device__ __nv_bfloat16 g_K[BHEADS * SEQ * DH]; // pre-scaled by CSC
__device__ __nv_bfloat16 g_Q[BHEADS * SEQ * DH];
__device__ __nv_bfloat16 g_V[BHEADS * SEQ * DH];

// ---------------- helpers ----------------
DINL uint32_t swz(uint32_t r, uint32_t cByte) {
    return r * 128u + (cByte ^ ((r & 7u) << 4));
}

DINL void cpa16(uint32_t dst, const void* src) {
    asm volatile("cp.async.cg.shared.global [%0], [%1], 16;\n" :: "r"(dst), "l"(src));
}
DINL void cpa_commit() { asm volatile("cp.async.commit_group;\n"); }
template <int N> DINL void cpa_wait() { asm volatile("cp.async.wait_group %0;\n" :: "n"(N)); }

DINL void ldm4(uint32_t addr, uint32_t& r0, uint32_t& r1, uint32_t& r2, uint32_t& r3) {
    asm volatile("ldmatrix.sync.aligned.m8n8.x4.shared.b16 {%0,%1,%2,%3}, [%4];"
                 : "=r"(r0), "=r"(r1), "=r"(r2), "=r"(r3) : "r"(addr));
}
DINL void ldm4t(uint32_t addr, uint32_t& r0, uint32_t& r1, uint32_t& r2, uint32_t& r3) {
    asm volatile("ldmatrix.sync.aligned.m8n8.x4.trans.shared.b16 {%0,%1,%2,%3}, [%4];"
                 : "=r"(r0), "=r"(r1), "=r"(r2), "=r"(r3) : "r"(addr));
}

DINL void mma_bf16(float* c, uint32_t a0, uint32_t a1, uint32_t a2, uint32_t a3,
                   uint32_t b0, uint32_t b1) {
    asm volatile(
        "mma.sync.aligned.m16n8k16.row.col.f32.bf16.bf16.f32 "
        "{%0,%1,%2,%3}, {%4,%5,%6,%7}, {%8,%9}, {%0,%1,%2,%3};"
        : "+f"(c[0]), "+f"(c[1]), "+f"(c[2]), "+f"(c[3])
        : "r"(a0), "r"(a1), "r"(a2), "r"(a3), "r"(b0), "r"(b1));
}

DINL void mma_bf16_z(float* d, const float* z,
                     uint32_t a0, uint32_t a1, uint32_t a2, uint32_t a3,
                     uint32_t b0, uint32_t b1) {
    asm volatile(
        "mma.sync.aligned.m16n8k16.row.col.f32.bf16.bf16.f32 "
        "{%0,%1,%2,%3}, {%4,%5,%6,%7}, {%8,%9}, {%10,%11,%12,%13};"
        : "=f"(d[0]), "=f"(d[1]), "=f"(d[2]), "=f"(d[3])
        : "r"(a0), "r"(a1), "r"(a2), "r"(a3), "r"(b0), "r"(b1),
          "f"(z[0]), "f"(z[1]), "f"(z[2]), "f"(z[3]));
}

DINL float rcpf_(float x) { float y; asm("rcp.approx.f32 %0, %1;" : "=f"(y) : "f"(x)); return y; }

DINL uint32_t packbf(float lo, float hi) {
    __nv_bfloat162 t = __floats2bfloat162_rn(lo, hi);
    return *reinterpret_cast<uint32_t*>(&t);
}

DINL uint32_t ex2bf2_(uint32_t x) {
    uint32_t y;
    asm("ex2.approx.ftz.bf16x2 %0, %1;" : "=r"(y) : "r"(x));
    return y;
}

// ---------------- merged, vectorized convert kernel (8 elems/thread) ----------------
__global__ void cvt_all_kernel(const float* __restrict__ x,
                               const float* __restrict__ Wc, const float* __restrict__ bc,
                               const float* __restrict__ Wv, const float* __restrict__ bv) {
    int i = blockIdx.x * 256 + threadIdx.x;
    if (i < XV) {
        const float4* src = reinterpret_cast<const float4*>(x) + (size_t)i * 2;
        float4 a = src[0];
        float4 b = src[1];
        uint4 o;
        o.x = packbf(a.x, a.y);
        o.y = packbf(a.z, a.w);
        o.z = packbf(b.x, b.y);
        o.w = packbf(b.z, b.w);
        reinterpret_cast<uint4*>(g_X)[i] = o;
    } else if (i < XV + WV) {
        int j = i - XV;
        int e = j * 8;
        int row = e >> 9;
        int col = e & 511;               // 512 % 8 == 0 -> vec never crosses a row
        const float* srcp = (row < DMODEL) ? (Wv + (size_t)row * DMODEL + col)
                                           : (Wc + (size_t)(row - DMODEL) * DMODEL + col);
        const float4* src = reinterpret_cast<const float4*>(srcp);
        float4 a = src[0];
        float4 b = src[1];
        uint4 o;
        o.x = packbf(a.x, a.y);
        o.y = packbf(a.z, a.w);
        o.z = packbf(b.x, b.y);
        o.w = packbf(b.z, b.w);
        reinterpret_cast<uint4*>(g_W)[j] = o;
        if (e < NOUT) {
#pragma unroll
            for (int t = 0; t < 8; t++) {
                int n = e + t;
                g_bias[n] = (n < DMODEL) ? bv[n] : bc[n - DMODEL];
            }
        }
    }
}

// ---------------- projection GEMM: C[8192,1536] = X @ W^T + bias ----------------
// CTA tile 128(M) x 64(N), BK=64, 8 warps (4x2), warp tile 32x32. (Measured-best config.)
__global__ __launch_bounds__(256) void proj_kernel() {
    __shared__ __nv_bfloat16 As[2][128 * 64];
    __shared__ __nv_bfloat16 Bs[2][64 * 64];

    const int tid = threadIdx.x;
    const int lane = tid & 31;
    const int wid = tid >> 5;
    const int m0 = blockIdx.x * 128;
    const int n0 = blockIdx.y * 64;
    const int wm = (wid & 3) * 32;
    const int wn = (wid >> 2) * 32;

    uint32_t asb[2], bsb[2];
    asb[0] = (uint32_t)__cvta_generic_to_shared(As[0]);
    asb[1] = (uint32_t)__cvta_generic_to_shared(As[1]);
    bsb[0] = (uint32_t)__cvta_generic_to_shared(Bs[0]);
    bsb[1] = (uint32_t)__cvta_generic_to_shared(Bs[1]);

    auto issue = [&](int kc, int buf) {
        const int k0 = kc * 64;
#pragma unroll
        for (int i = 0; i < 4; i++) {
            int id = tid + i * 256;
            int r = id >> 3, ch = id & 7;
            cpa16(asb[buf] + swz(r, ch * 16), g_X + (size_t)(m0 + r) * DMODEL + k0 + ch * 8);
        }
#pragma unroll
        for (int i = 0; i < 2; i++) {
            int id = tid + i * 256;
            int r = id >> 3, ch = id & 7;
            cpa16(bsb[buf] + swz(r, ch * 16), g_W + (size_t)(n0 + r) * DMODEL + k0 + ch * 8);
        }
    };

    float acc[2][4][4] = {};

    issue(0, 0);
    cpa_commit();

    for (int kc = 0; kc < 8; kc++) {
        const int buf = kc & 1;
        __syncthreads();
        if (kc + 1 < 8) {
            issue(kc + 1, buf ^ 1);
            cpa_commit();
            cpa_wait<1>();
        } else {
            cpa_wait<0>();
        }
        __syncthreads();

#pragma unroll
        for (int kk = 0; kk < 4; kk++) {
            uint32_t a[2][4];
#pragma unroll
            for (int mt = 0; mt < 2; mt++) {
                int r = wm + mt * 16 + (lane & 7) + ((lane >> 3) & 1) * 8;
                int ch = kk * 2 + (lane >> 4);
                ldm4(asb[buf] + swz(r, ch * 16), a[mt][0], a[mt][1], a[mt][2], a[mt][3]);
            }
            uint32_t b[4][2];
#pragma unroll
            for (int p = 0; p < 2; p++) {
                int r = wn + p * 16 + (lane & 7) + ((lane >> 4) & 1) * 8;
                int ch = kk * 2 + ((lane >> 3) & 1);
                uint32_t r0, r1, r2, r3;
                ldm4(bsb[buf] + swz(r, ch * 16), r0, r1, r2, r3);
                b[p * 2][0] = r0; b[p * 2][1] = r1;
                b[p * 2 + 1][0] = r2; b[p * 2 + 1][1] = r3;
            }
#pragma unroll
            for (int mt = 0; mt < 2; mt++)
#pragma unroll
                for (int nt = 0; nt < 4; nt++)
                    mma_bf16(acc[mt][nt], a[mt][0], a[mt][1], a[mt][2], a[mt][3],
                             b[nt][0], b[nt][1]);
        }
    }

    // epilogue: bias + scatter into per-head layouts (bf16); K gets pre-scaled by CSC
#pragma unroll
    for (int mt = 0; mt < 2; mt++) {
#pragma unroll
        for (int nt = 0; nt < 4; nt++) {
            int n = n0 + wn + nt * 8 + (lane & 3) * 2;
            float b0 = g_bias[n], b1 = g_bias[n + 1];
            int region = n >> 9;            // 0:K  1:Q  2:V
            int col = n & 511;
            int h = col >> 6;
            int d = col & 63;
            __nv_bfloat16* dst = (region == 0) ? g_K : ((region == 1) ? g_Q : g_V);
            float sc = (region == 0) ? CSC : 1.0f;
#pragma unroll
            for (int half = 0; half < 2; half++) {
                int m = m0 + wm + mt * 16 + (lane >> 2) + half * 8;
                int bb = m >> 12;
                int s = m & 4095;
                float v0 = (acc[mt][nt][half * 2 + 0] + b0) * sc;
                float v1 = (acc[mt][nt][half * 2 + 1] + b1) * sc;
                size_t off = ((size_t)(bb * NH + h) * SEQ + s) * DH + d;
                *reinterpret_cast<__nv_bfloat162*>(dst + off) = __floats2bfloat162_rn(v0, v1);
            }
        }
    }
}

// ---------------- attention kernel ----------------
// grid (SEQ/128, BHEADS); 128 threads (4 warps), each warp owns 32 i-rows
// (two 16-row strips sharing every Q/V fragment). 2 CTAs/SM. JTILE=128.
// No-max log2-domain softmax; l via tensor-core P@ones.
__global__ __launch_bounds__(128, 2) void attn_kernel(const float* __restrict__ mfeat,
                                                      float* __restrict__ out) {
    extern __shared__ char smem[];
    const uint32_t smb = (uint32_t)__cvta_generic_to_shared(smem);
    const uint32_t ksb = smb + KSM_OFF;
    const uint32_t qsb[2] = { smb + QSM_OFF0, smb + QSM_OFF1 };
    const uint32_t vsb[2] = { smb + VSM_OFF0, smb + VSM_OFF1 };

    const int tid = threadIdx.x;
    const int lane = tid & 31;
    const int wid = tid >> 5;      // 0..3
    const int i0 = blockIdx.x * ITILE;
    const int bh = blockIdx.y;

    const __nv_bfloat16* Kg = g_K + (size_t)bh * SEQ * DH;
    const __nv_bfloat16* Qg = g_Q + (size_t)bh * SEQ * DH;
    const __nv_bfloat16* Vg = g_V + (size_t)bh * SEQ * DH;

    // K tile load (128 rows x 8 chunks, resident; fragments hoisted)
#pragma unroll
    for (int i = 0; i < 8; i++) {
        int id = tid + i * 128;
        int r = id >> 3, ch = id & 7;
        cpa16(ksb + swz(r, ch * 16), Kg + (size_t)(i0 + r) * DH + ch * 8);
    }
    cpa_commit();

    auto issue_qv = [&](int jt, int buf) {
        int j0 = jt * JTILE;
#pragma unroll
        for (int i = 0; i < 8; i++) {
            int id = tid + i * 128;
            int r = id >> 3, ch = id & 7;
            cpa16(qsb[buf] + swz(r, ch * 16), Qg + (size_t)(j0 + r) * DH + ch * 8);
            cpa16(vsb[buf] + swz(r, ch * 16), Vg + (size_t)(j0 + r) * DH + ch * 8);
        }
    };

    issue_qv(0, 0);
    cpa_commit();

    // wait for K, hoist K fragments for both strips
    cpa_wait<1>();
    __syncthreads();
    uint32_t kf[2][4][4];
#pragma unroll
    for (int st = 0; st < 2; st++) {
#pragma unroll
        for (int kk = 0; kk < 4; kk++) {
            int r = wid * 32 + st * 16 + (lane & 7) + ((lane >> 3) & 1) * 8;
            int ch = kk * 2 + (lane >> 4);
            ldm4(ksb + swz(r, ch * 16), kf[st][kk][0], kf[st][kk][1], kf[st][kk][2], kf[st][kk][3]);
        }
    }

    const uint32_t ONES2 = 0x3F803F80u;   // bf16x2 {1.0, 1.0}
    float zq[4] = {0.f, 0.f, 0.f, 0.f};   // persistent zero quad (C for first QK MMA)
    float lacc[2][4] = {};                // per-strip row sums via tensor core
    float o[2][8][4] = {};

    const int NT = SEQ / JTILE;           // 32
    constexpr int NP = JTILE / 16;        // 8 16-j blocks per stage

    for (int jt = 0; jt < NT; jt++) {
        const int buf = jt & 1;
        if (jt + 1 < NT) {
            issue_qv(jt + 1, buf ^ 1);
            cpa_commit();
            cpa_wait<1>();
        } else {
            cpa_wait<0>();
        }
        __syncthreads();

#pragma unroll
        for (int p = 0; p < NP; p++) {
            // ---- S(32x16) = K strips @ Q_block^T ----
            float s[2][2][4];
#pragma unroll
            for (int kk = 0; kk < 4; kk++) {
                int r = p * 16 + (lane & 7) + ((lane >> 4) & 1) * 8;
                int ch = kk * 2 + ((lane >> 3) & 1);
                uint32_t b0, b1, b2, b3;
                ldm4(qsb[buf] + swz(r, ch * 16), b0, b1, b2, b3);
                if (kk == 0) {
#pragma unroll
                    for (int st = 0; st < 2; st++) {
                        mma_bf16_z(s[st][0], zq, kf[st][0][0], kf[st][0][1], kf[st][0][2], kf[st][0][3], b0, b1);
                        mma_bf16_z(s[st][1], zq, kf[st][0][0], kf[st][0][1], kf[st][0][2], kf[st][0][3], b2, b3);
                    }
                } else {
#pragma unroll
                    for (int st = 0; st < 2; st++) {
                        mma_bf16(s[st][0], kf[st][kk][0], kf[st][kk][1], kf[st][kk][2], kf[st][kk][3], b0, b1);
                        mma_bf16(s[st][1], kf[st][kk][0], kf[st][kk][1], kf[st][kk][2], kf[st][kk][3], b2, b3);
                    }
                }
            }

            // ---- P = 2^S (bf16x2 MUFU) ----
            uint32_t pa[2][4];
#pragma unroll
            for (int st = 0; st < 2; st++) {
                pa[st][0] = ex2bf2_(packbf(s[st][0][0], s[st][0][1]));
                pa[st][1] = ex2bf2_(packbf(s[st][0][2], s[st][0][3]));
                pa[st][2] = ex2bf2_(packbf(s[st][1][0], s[st][1][1]));
                pa[st][3] = ex2bf2_(packbf(s[st][1][2], s[st][1][3]));
            }

            // ---- O += P(32x16) @ V_block(16x64) ----
#pragma unroll
            for (int cb = 0; cb < 8; cb += 2) {
                int r = p * 16 + (lane & 7) + ((lane >> 3) & 1) * 8;
                int ch = cb + (lane >> 4);
                uint32_t b0, b1, b2, b3;
                ldm4t(vsb[buf] + swz(r, ch * 16), b0, b1, b2, b3);
#pragma unroll
                for (int st = 0; st < 2; st++) {
                    mma_bf16(o[st][cb + 0], pa[st][0], pa[st][1], pa[st][2], pa[st][3], b0, b1);
                    mma_bf16(o[st][cb + 1], pa[st][0], pa[st][1], pa[st][2], pa[st][3], b2, b3);
                }
            }

            // ---- l += P @ ones ----
#pragma unroll
            for (int st = 0; st < 2; st++)
                mma_bf16(lacc[st], pa[st][0], pa[st][1], pa[st][2], pa[st][3], ONES2, ONES2);
        }
        __syncthreads();
    }

    // ---- epilogue: out = m_feats + O / l ----
    const int b = bh >> 3;
    const int h = bh & 7;
#pragma unroll
    for (int st = 0; st < 2; st++) {
        float rl0 = rcpf_(lacc[st][0]);
        float rl1 = rcpf_(lacc[st][2]);
        const int gi0 = i0 + wid * 32 + st * 16 + (lane >> 2);
#pragma unroll
        for (int nt = 0; nt < 8; nt++) {
            int dcol = h * 64 + nt * 8 + (lane & 3) * 2;
            size_t idx0 = ((size_t)(b * SEQ + gi0)) * DMODEL + dcol;
            size_t idx1 = idx0 + (size_t)8 * DMODEL;
            float2 f0 = *reinterpret_cast<const float2*>(mfeat + idx0);
            float2 f1 = *reinterpret_cast<const float2*>(mfeat + idx1);
            float2 w0 = make_float2(f0.x + o[st][nt][0] * rl0, f0.y + o[st][nt][1] * rl0);
            float2 w1 = make_float2(f1.x + o[st][nt][2] * rl1, f1.y + o[st][nt][3] * rl1);
            *reinterpret_cast<float2*>(out + idx0) = w0;
            *reinterpret_cast<float2*>(out + idx1) = w1;
        }
    }
}

// ---------------- launch ----------------
extern "C" void kernel_launch(void* const* d_in, const int* in_sizes, int n_in,
                              void* d_out, int out_size) {
    const float* mf = (const float*)d_in[0];
    const float* Wc = (const float*)d_in[1];
    const float* bc = (const float*)d_in[2];
    const float* Wv = (const float*)d_in[3];
    const float* bv = (const float*)d_in[4];
    float* out = (float*)d_out;

    cudaFuncSetAttribute(attn_kernel, cudaFuncAttributeMaxDynamicSharedMemorySize, SMEM_BYTES);

    cvt_all_kernel<<<(XV + WV + 255) / 256, 256>>>(mf, Wc, bc, Wv, bv);
    proj_kernel<<<dim3(MROWS / 128, NOUT / 64), 256>>>();
    attn_kernel<<<dim3(SEQ / ITILE, BHEADS), 128, SMEM_BYTES>>>(mf, out);
}